// round 6
// baseline (speedup 1.0000x reference)
#include <cuda_runtime.h>
#include <cuda_bf16.h>
#include <cstdint>

// Problem constants
#define BB 64
#define TT 512
#define DD 1024
#define HH 1024
#define NG 4096   // 4*H
#define KT 1024   // K depth of every GEMM (D == H == 1024)
#define NBLK 128  // CTAs in recurrent kernel (each owns 32 packed gate cols)

// ---------------------------------------------------------------------------
// Device-global scratch (no runtime allocation allowed)
// ---------------------------------------------------------------------------
__device__ float g_Z  [(size_t)BB * TT * NG];   // 512 MB: precomputed x-part of gates (packed cols)
__device__ float g_y0 [(size_t)BB * TT * HH];   // 128 MB: layer-0 outputs (layer-1 inputs)
__device__ float g_Wxp[2][(size_t)KT * NG];     // input weights hi (tf32), packed row-major
__device__ float g_Wxr[2][(size_t)KT * NG];     // input weights lo residual (tf32)
__device__ float g_Whf[2][(size_t)KT * NG];     // recurrent weights hi (tf32), fragment-major
__device__ __nv_bfloat16 g_Whr[2][(size_t)KT * NG]; // recurrent weights lo residual (bf16), same idx
__device__ float g_bp [2][NG];                  // packed bias per layer
__device__ float g_hA [2][BB * HH];             // h ping
__device__ float g_hB [2][BB * HH];             // h pong
__device__ float g_cS [2][BB * HH];             // c state (CTA-exclusive cols)
__device__ int   g_len[BB];                     // normalized lengths (int32)

// Grid barrier state
__device__ volatile unsigned g_gen;
__device__ unsigned g_count;

// ---------------------------------------------------------------------------
// Helpers
// ---------------------------------------------------------------------------
__device__ __forceinline__ float to_tf32(float x) {
    float r;
    asm("cvt.rna.tf32.f32 %0, %1;" : "=f"(r) : "f"(x));
    return r;
}

__device__ __forceinline__ void mma8(float* c, const uint32_t* a, const uint32_t* b) {
    asm volatile(
        "mma.sync.aligned.m16n8k8.row.col.f32.tf32.tf32.f32 "
        "{%0,%1,%2,%3},{%4,%5,%6,%7},{%8,%9},{%0,%1,%2,%3};\n"
        : "+f"(c[0]), "+f"(c[1]), "+f"(c[2]), "+f"(c[3])
        : "r"(a[0]), "r"(a[1]), "r"(a[2]), "r"(a[3]), "r"(b[0]), "r"(b[1]));
}

__device__ __forceinline__ void cp16(void* smem_dst, const void* gmem_src) {
    unsigned s = (unsigned)__cvta_generic_to_shared(smem_dst);
    asm volatile("cp.async.cg.shared.global [%0], [%1], 16;\n" :: "r"(s), "l"(gmem_src));
}

__device__ __forceinline__ float sigm(float x) { return 1.0f / (1.0f + __expf(-x)); }

// Sense-reversal grid barrier (all NBLK CTAs resident in one wave)
__device__ __forceinline__ void grid_barrier() {
    __threadfence();
    __syncthreads();
    if (threadIdx.x == 0) {
        unsigned gen = g_gen;
        if (atomicInc(&g_count, NBLK - 1) == NBLK - 1) {
            g_gen = gen + 1;                 // release (wraps g_count to 0)
        } else {
            while (g_gen == gen) __nanosleep(64);
        }
        __threadfence();
    }
    __syncthreads();
}

// ---------------------------------------------------------------------------
// Lengths normalization: autodetect int64 vs int32 payload.
// ---------------------------------------------------------------------------
__global__ void norm_lengths(const long long* __restrict__ l64) {
    const int* l32 = (const int*)l64;
    __shared__ int bad;
    if (threadIdx.x == 0) bad = 0;
    __syncthreads();
    if (threadIdx.x < 32) {
        long long v = l64[threadIdx.x];
        if (v < 1 || v > TT) atomicOr(&bad, 1);
    }
    __syncthreads();
    int L = bad ? l32[threadIdx.x] : (int)l64[threadIdx.x];
    g_len[threadIdx.x] = L;
}

// ---------------------------------------------------------------------------
// Weight packing with hi/lo precision split.
// Wx half: packed column p = u*4+g, row-major: hi tf32 + lo tf32 residual.
// Wh half: per-CTA MMA-fragment-major: hi tf32 + lo bf16 residual.
// ---------------------------------------------------------------------------
__global__ void pack_kernel(const float* __restrict__ W, const float* __restrict__ b, int layer) {
    int idx = blockIdx.x * 256 + threadIdx.x;
    if (idx < 2 * KT * NG) {
        int k = idx >> 12;        // row 0..2047
        int p = idx & 4095;       // packed column
        int u = p >> 2, g = p & 3;
        float v  = W[(size_t)k * NG + g * HH + u];
        float hi = to_tf32(v);
        float lo = v - hi;
        if (k < KT) {
            g_Wxp[layer][(size_t)k * NG + p] = hi;
            g_Wxr[layer][(size_t)k * NG + p] = to_tf32(lo);
        } else {
            int kk = k - KT;
            int n0b = p >> 5, c = p & 31;
            int wn = c >> 4, nt = (c >> 3) & 1, gg = c & 7;
            int kt = kk >> 5, kr = kk & 31;
            int ks = kr >> 3, tr = kr & 7;
            int r = tr >> 2, tg = tr & 3;
            int lane = gg * 4 + tg;
            int f = ((ks * 2 + nt) * 2 + wn) * 64 + lane * 2 + r;
            g_Whf[layer][(size_t)n0b * 32768 + kt * 1024 + f] = hi;
            g_Whr[layer][(size_t)n0b * 32768 + kt * 1024 + f] = __float2bfloat16(lo);
        }
    }
    if (idx < NG) {
        int u = idx >> 2, g = idx & 3;
        g_bp[layer][idx] = b[g * HH + u];
    }
}

__global__ void init_state() {
    int i = blockIdx.x * 256 + threadIdx.x;
    if (i == 0) { g_gen = 0; g_count = 0; }
    if (i < BB * HH) {
        g_hA[0][i] = 0.f; g_hA[1][i] = 0.f;
        g_cS[0][i] = 0.f; g_cS[1][i] = 0.f;
    }
}

// ---------------------------------------------------------------------------
// Pre-GEMM with 3-MMA split: g_Z = A.(Whi+Wlo) + bias, A split in-register.
// Block tile 64x128, BK=32, 256 threads (8 warps: 4m x 2n).
// ---------------------------------------------------------------------------
__global__ __launch_bounds__(256, 1)
void pregemm_kernel(const float* __restrict__ x, int layer) {
    __shared__ float a_s[64 * 36];     // raw fp32 A tile
    __shared__ float w_s[32 * 132];    // W hi
    __shared__ float w_r[32 * 132];    // W lo

    const float* __restrict__ A   = layer ? g_y0 : x;
    const float* __restrict__ Wp  = g_Wxp[layer];
    const float* __restrict__ Wr  = g_Wxr[layer];

    int tid = threadIdx.x, warp = tid >> 5, lane = tid & 31;
    int wm = warp & 3, wn = warp >> 2;
    int gg = lane >> 2, tg = lane & 3;
    size_t m0 = (size_t)blockIdx.y * 64;
    int n0 = blockIdx.x * 128;

    float acc[32];
#pragma unroll
    for (int i = 0; i < 32; i++) acc[i] = 0.f;

    for (int kt = 0; kt < KT; kt += 32) {
#pragma unroll
        for (int r = 0; r < 2; r++) {
            int q = tid + (r << 8);
            int row = q >> 3, c = (q & 7) << 2;
            *(float4*)(a_s + row * 36 + c) =
                *(const float4*)(A + (m0 + row) * KT + kt + c);
        }
#pragma unroll
        for (int r = 0; r < 4; r++) {
            int q = tid + (r << 8);
            int row = q >> 5, c = (q & 31) << 2;
            *(float4*)(w_s + row * 132 + c) =
                *(const float4*)(Wp + (size_t)(kt + row) * NG + n0 + c);
            *(float4*)(w_r + row * 132 + c) =
                *(const float4*)(Wr + (size_t)(kt + row) * NG + n0 + c);
        }
        __syncthreads();

#pragma unroll
        for (int ks = 0; ks < 4; ks++) {
            int k0 = ks * 8;
            int ar = wm * 16 + gg;
            float v0 = a_s[ar * 36 + k0 + tg];
            float v1 = a_s[(ar + 8) * 36 + k0 + tg];
            float v2 = a_s[ar * 36 + k0 + tg + 4];
            float v3 = a_s[(ar + 8) * 36 + k0 + tg + 4];
            float h0 = to_tf32(v0), h1 = to_tf32(v1), h2 = to_tf32(v2), h3 = to_tf32(v3);
            uint32_t af_hi[4] = { __float_as_uint(h0), __float_as_uint(h1),
                                  __float_as_uint(h2), __float_as_uint(h3) };
            uint32_t af_lo[4] = { __float_as_uint(to_tf32(v0 - h0)),
                                  __float_as_uint(to_tf32(v1 - h1)),
                                  __float_as_uint(to_tf32(v2 - h2)),
                                  __float_as_uint(to_tf32(v3 - h3)) };
#pragma unroll
            for (int nt = 0; nt < 8; nt++) {
                int bc = wn * 64 + nt * 8 + gg;
                uint32_t bf_hi[2] = { __float_as_uint(w_s[(k0 + tg) * 132 + bc]),
                                      __float_as_uint(w_s[(k0 + tg + 4) * 132 + bc]) };
                uint32_t bf_lo[2] = { __float_as_uint(w_r[(k0 + tg) * 132 + bc]),
                                      __float_as_uint(w_r[(k0 + tg + 4) * 132 + bc]) };
                mma8(acc + nt * 4, af_hi, bf_hi);
                mma8(acc + nt * 4, af_hi, bf_lo);
                mma8(acc + nt * 4, af_lo, bf_hi);
            }
        }
        __syncthreads();
    }

#pragma unroll
    for (int nt = 0; nt < 8; nt++) {
        int col = n0 + wn * 64 + nt * 8 + 2 * tg;
        size_t row = m0 + wm * 16 + gg;
        float bv0 = g_bp[layer][col], bv1 = g_bp[layer][col + 1];
        g_Z[row * NG + col]           = acc[nt * 4 + 0] + bv0;
        g_Z[row * NG + col + 1]       = acc[nt * 4 + 1] + bv1;
        g_Z[(row + 8) * NG + col]     = acc[nt * 4 + 2] + bv0;
        g_Z[(row + 8) * NG + col + 1] = acc[nt * 4 + 3] + bv1;
    }
}

// ---------------------------------------------------------------------------
// Persistent recurrent kernel, 3-MMA split precision.
// Smem: W hi 128KB + W lo (bf16) 64KB + h double buffer 18KB = 215KB.
// ---------------------------------------------------------------------------
#define SMEM_WF 32768
#define SMEM_WL 16384                 // 32768 bf16 in float-slot units
#define HSTRIDE 36
#define HBUF (64 * HSTRIDE)
#define RSMEM_BYTES ((SMEM_WF + SMEM_WL + 2 * HBUF) * 4)

__global__ __launch_bounds__(256, 1)
void recurrent_kernel(int layer, float* __restrict__ dout) {
    extern __shared__ float sm[];
    float* Wf = sm;                                    // hi, fragment-major
    __nv_bfloat16* Wl = (__nv_bfloat16*)(sm + SMEM_WF);// lo, same indexing
    float* h_s0 = sm + SMEM_WF + SMEM_WL;
    float* h_s1 = sm + SMEM_WF + SMEM_WL + HBUF;
    float* zs   = h_s0;   // epilogue staging reuses buffer 0

    const float* __restrict__ Wsrc = g_Whf[layer] + (size_t)blockIdx.x * SMEM_WF;
    const __nv_bfloat16* __restrict__ Wlsrc = g_Whr[layer] + (size_t)blockIdx.x * SMEM_WF;
    float* __restrict__ cbuf = g_cS[layer];
    float* __restrict__ yout = layer ? dout : g_y0;

    int tid = threadIdx.x, warp = tid >> 5, lane = tid & 31;
    int wm = warp & 3, wn = warp >> 2;
    int gg = lane >> 2, tg = lane & 3;
    int n0 = blockIdx.x * 32;

    // One-time W slice load: hi 128KB + lo 64KB
    for (int i = tid * 4; i < SMEM_WF; i += 1024) cp16(&Wf[i], Wsrc + i);
    for (int i = tid * 8; i < 2 * SMEM_WL; i += 2048) cp16(&Wl[i], Wlsrc + i);
    asm volatile("cp.async.commit_group;\n");

    int lb0 = g_len[tid >> 3];
    int lb1 = g_len[32 + (tid >> 3)];

    for (int t = 0; t < TT; t++) {
        const float* __restrict__ hin  = (t & 1) ? g_hB[layer] : g_hA[layer];
        float* __restrict__       hout = (t & 1) ? g_hA[layer] : g_hB[layer];

        float acc[8];
#pragma unroll
        for (int i = 0; i < 8; i++) acc[i] = 0.f;

        // first h tile
        {
#pragma unroll
            for (int rr = 0; rr < 2; rr++) {
                int q = tid + (rr << 8);
                int row = q >> 3, c = (q & 7) << 2;
                cp16(&h_s0[row * HSTRIDE + c], hin + (size_t)row * HH + c);
            }
            asm volatile("cp.async.commit_group;\n");
        }

#pragma unroll 2
        for (int ktile = 0; ktile < 32; ktile++) {
            float* cb = (ktile & 1) ? h_s1 : h_s0;
            float* nb = (ktile & 1) ? h_s0 : h_s1;
            if (ktile < 31) {
                int kt = (ktile + 1) * 32;
#pragma unroll
                for (int rr = 0; rr < 2; rr++) {
                    int q = tid + (rr << 8);
                    int row = q >> 3, c = (q & 7) << 2;
                    cp16(&nb[row * HSTRIDE + c], hin + (size_t)row * HH + kt + c);
                }
                asm volatile("cp.async.commit_group;\n");
                asm volatile("cp.async.wait_group 1;\n");
            } else {
                asm volatile("cp.async.wait_group 0;\n");
            }
            __syncthreads();

            int fb = ktile * 1024 + wn * 64 + lane * 2;
#pragma unroll
            for (int ks = 0; ks < 4; ks++) {
                int k0 = ks * 8;
                int ar = wm * 16 + gg;
                float v0 = cb[ar * HSTRIDE + k0 + tg];
                float v1 = cb[(ar + 8) * HSTRIDE + k0 + tg];
                float v2 = cb[ar * HSTRIDE + k0 + tg + 4];
                float v3 = cb[(ar + 8) * HSTRIDE + k0 + tg + 4];
                float h0 = to_tf32(v0), h1 = to_tf32(v1), h2 = to_tf32(v2), h3 = to_tf32(v3);
                uint32_t af_hi[4] = { __float_as_uint(h0), __float_as_uint(h1),
                                      __float_as_uint(h2), __float_as_uint(h3) };
                uint32_t af_lo[4] = { __float_as_uint(to_tf32(v0 - h0)),
                                      __float_as_uint(to_tf32(v1 - h1)),
                                      __float_as_uint(to_tf32(v2 - h2)),
                                      __float_as_uint(to_tf32(v3 - h3)) };
#pragma unroll
                for (int nt = 0; nt < 2; nt++) {
                    int fi = fb + (ks * 2 + nt) * 128;
                    float2 whi = *(const float2*)(Wf + fi);
                    float2 wlo = __bfloat1622float2(*(const __nv_bfloat162*)(Wl + fi));
                    uint32_t bf_hi[2] = { __float_as_uint(whi.x), __float_as_uint(whi.y) };
                    uint32_t bf_lo[2] = { __float_as_uint(wlo.x), __float_as_uint(wlo.y) };
                    mma8(acc + nt * 4, af_hi, bf_hi);
                    mma8(acc + nt * 4, af_hi, bf_lo);
                    mma8(acc + nt * 4, af_lo, bf_hi);
                }
            }
            __syncthreads();
        }

        // Stage accumulators so each thread can gather full (i,j,f,o)
#pragma unroll
        for (int nt = 0; nt < 2; nt++) {
            int col = wn * 16 + nt * 8 + 2 * tg;
            int row = wm * 16 + gg;
            zs[row * 32 + col]           = acc[nt * 4 + 0];
            zs[row * 32 + col + 1]       = acc[nt * 4 + 1];
            zs[(row + 8) * 32 + col]     = acc[nt * 4 + 2];
            zs[(row + 8) * 32 + col + 1] = acc[nt * 4 + 3];
        }
        __syncthreads();

        // Fused gate epilogue: 512 (b, unit) items / 256 threads
#pragma unroll
        for (int rr = 0; rr < 2; rr++) {
            int it = tid + (rr << 8);
            int b = it >> 3, u = it & 7;
            int uglob = (n0 >> 2) + u;
            float4 zp = *(const float4*)(g_Z + ((size_t)b * TT + t) * NG + n0 + u * 4);
            float zi = zs[b * 32 + u * 4 + 0] + zp.x;
            float zj = zs[b * 32 + u * 4 + 1] + zp.y;
            float zf = zs[b * 32 + u * 4 + 2] + zp.z;
            float zo = zs[b * 32 + u * 4 + 3] + zp.w;

            float co = cbuf[b * HH + uglob];
            float ho = hin[b * HH + uglob];

            float ig = sigm(zi);
            float fg = sigm(zf + 1.0f);     // FORGET_BIAS
            float og = sigm(zo);
            float cn = co * fg + ig * tanhf(zj);
            float hn = tanhf(cn) * og;

            int lb = rr ? lb1 : lb0;
            bool m = t < lb;
            cbuf[b * HH + uglob] = m ? cn : co;
            hout[b * HH + uglob] = m ? hn : ho;
            yout[((size_t)b * TT + t) * HH + uglob] = m ? hn : 0.f;
        }

        grid_barrier();
    }
}

// ---------------------------------------------------------------------------
// Copy final h/c stacks into d_out after y1. T=512 even -> final h lives in g_hA.
// ---------------------------------------------------------------------------
__global__ void finalize_kernel(float* __restrict__ dout) {
    int i = blockIdx.x * 256 + threadIdx.x;
    const size_t YN = (size_t)BB * TT * HH;
    if (i < 2 * BB * HH) {
        int layer = i >> 16;       // BB*HH = 65536 per layer
        int j = i & 65535;
        dout[YN + i]               = g_hA[layer][j];
        dout[YN + 2 * BB * HH + i] = g_cS[layer][j];
    }
}

// ---------------------------------------------------------------------------
// kernel_launch: identify inputs by element count, 9 graph nodes total.
// ---------------------------------------------------------------------------
extern "C" void kernel_launch(void* const* d_in, const int* in_sizes, int n_in,
                              void* d_out, int out_size) {
    int ix = -1, il = -1, iw[2] = {-1, -1}, ib[2] = {-1, -1};
    for (int i = 0; i < n_in; i++) {
        int n = in_sizes[i];
        if (n == BB * TT * DD)            { if (ix < 0) ix = i; }
        else if (n == BB)                 { if (il < 0) il = i; }
        else if (n == (DD + HH) * NG)     { if (iw[0] < 0) iw[0] = i; else if (iw[1] < 0) iw[1] = i; }
        else if (n == NG)                 { if (ib[0] < 0) ib[0] = i; else if (ib[1] < 0) ib[1] = i; }
    }
    if (ix < 0) ix = 0;
    if (il < 0) il = 1;
    if (iw[0] < 0) iw[0] = 2;
    if (ib[0] < 0) ib[0] = 3;
    if (iw[1] < 0) iw[1] = 4;
    if (ib[1] < 0) ib[1] = 5;

    const float*     x    = (const float*)d_in[ix];
    const long long* lens = (const long long*)d_in[il];
    const float*     W0   = (const float*)d_in[iw[0]];
    const float*     b0   = (const float*)d_in[ib[0]];
    const float*     W1   = (const float*)d_in[iw[1]];
    const float*     b1   = (const float*)d_in[ib[1]];
    float*           out  = (float*)d_out;

    cudaFuncSetAttribute(recurrent_kernel,
                         cudaFuncAttributeMaxDynamicSharedMemorySize, RSMEM_BYTES);

    norm_lengths<<<1, 64>>>(lens);
    pack_kernel<<<32768, 256>>>(W0, b0, 0);
    pack_kernel<<<32768, 256>>>(W1, b1, 1);
    init_state<<<256, 256>>>();

    pregemm_kernel<<<dim3(32, 512), 256>>>(x, 0);
    recurrent_kernel<<<NBLK, 256, RSMEM_BYTES>>>(0, out);

    pregemm_kernel<<<dim3(32, 512), 256>>>(x, 1);
    recurrent_kernel<<<NBLK, 256, RSMEM_BYTES>>>(1, out);

    finalize_kernel<<<512, 256>>>(out);
}

// round 7
// speedup vs baseline: 1.0408x; 1.0408x over previous
#include <cuda_runtime.h>
#include <cuda_bf16.h>
#include <cstdint>

// Problem constants
#define BB 64
#define TT 512
#define DD 1024
#define HH 1024
#define NG 4096   // 4*H
#define KT 1024   // K depth of every GEMM (D == H == 1024)
#define NBLK 128  // CTAs in recurrent kernel (each owns 32 packed gate cols)

// ---------------------------------------------------------------------------
// Device-global scratch (no runtime allocation allowed)
// ---------------------------------------------------------------------------
__device__ float g_Z  [(size_t)BB * TT * NG];   // 512 MB: precomputed x-part of gates (packed cols)
__device__ float g_y0 [(size_t)BB * TT * HH];   // 128 MB: layer-0 outputs (layer-1 inputs)
__device__ float g_Wxp[2][(size_t)KT * NG];     // input weights hi (tf32), packed row-major
__device__ float g_Wxr[2][(size_t)KT * NG];     // input weights lo residual (tf32)
__device__ float g_Whf[2][(size_t)KT * NG];     // recurrent weights hi (tf32), fragment-major
__device__ __nv_bfloat16 g_Whr[2][(size_t)KT * NG]; // recurrent weights lo residual (bf16), same idx
__device__ float g_bp [2][NG];                  // packed bias per layer
__device__ float g_hA [2][BB * HH];             // h ping
__device__ float g_hB [2][BB * HH];             // h pong
__device__ float g_cS [2][BB * HH];             // c state (CTA-exclusive cols)
__device__ int   g_len[BB];                     // normalized lengths (int32)

// Grid barrier state
__device__ volatile unsigned g_gen;
__device__ unsigned g_count;

// ---------------------------------------------------------------------------
// Helpers
// ---------------------------------------------------------------------------
__device__ __forceinline__ float to_tf32(float x) {
    float r;
    asm("cvt.rna.tf32.f32 %0, %1;" : "=f"(r) : "f"(x));
    return r;
}

__device__ __forceinline__ void mma8(float* c, const uint32_t* a, const uint32_t* b) {
    asm volatile(
        "mma.sync.aligned.m16n8k8.row.col.f32.tf32.tf32.f32 "
        "{%0,%1,%2,%3},{%4,%5,%6,%7},{%8,%9},{%0,%1,%2,%3};\n"
        : "+f"(c[0]), "+f"(c[1]), "+f"(c[2]), "+f"(c[3])
        : "r"(a[0]), "r"(a[1]), "r"(a[2]), "r"(a[3]), "r"(b[0]), "r"(b[1]));
}

__device__ __forceinline__ void cp16(void* smem_dst, const void* gmem_src) {
    unsigned s = (unsigned)__cvta_generic_to_shared(smem_dst);
    asm volatile("cp.async.cg.shared.global [%0], [%1], 16;\n" :: "r"(s), "l"(gmem_src));
}

__device__ __forceinline__ float sigm(float x) { return 1.0f / (1.0f + __expf(-x)); }

// Sense-reversal grid barrier (all NBLK CTAs resident in one wave)
__device__ __forceinline__ void grid_barrier() {
    __threadfence();
    __syncthreads();
    if (threadIdx.x == 0) {
        unsigned gen = g_gen;
        if (atomicInc(&g_count, NBLK - 1) == NBLK - 1) {
            g_gen = gen + 1;                 // release (wraps g_count to 0)
        } else {
            while (g_gen == gen) __nanosleep(64);
        }
        __threadfence();
    }
    __syncthreads();
}

// ---------------------------------------------------------------------------
// Setup: lengths normalization (int64/int32 autodetect) + state/barrier init.
// Single kernel so the profiler's capture slot lands on pregemm_kernel.
// ---------------------------------------------------------------------------
__global__ void setup_kernel(const long long* __restrict__ l64) {
    int i = blockIdx.x * 256 + threadIdx.x;
    if (i == 0) { g_gen = 0; g_count = 0; }
    if (i < BB * HH) {
        g_hA[0][i] = 0.f; g_hA[1][i] = 0.f;
        g_cS[0][i] = 0.f; g_cS[1][i] = 0.f;
    }
    if (blockIdx.x == 0 && threadIdx.x < BB) {
        const int* l32 = (const int*)l64;
        __shared__ int bad;
        if (threadIdx.x == 0) bad = 0;
        __syncwarp(0xFFFFFFFF);
        // threads 0..31 vote on dtype using first 32 int64 slots (256 B, safe)
        if (threadIdx.x < 32) {
            long long v = l64[threadIdx.x];
            if (v < 1 || v > TT) atomicOr(&bad, 1);
        }
        __syncthreads();
        int L = bad ? l32[threadIdx.x] : (int)l64[threadIdx.x];
        g_len[threadIdx.x] = L;
    }
}

// ---------------------------------------------------------------------------
// Weight packing with hi/lo precision split.
// Wx half: packed column p = u*4+g, row-major: hi tf32 + lo tf32 residual.
// Wh half: per-CTA MMA-fragment-major: hi tf32 + lo bf16 residual.
// ---------------------------------------------------------------------------
__global__ void pack_kernel(const float* __restrict__ W, const float* __restrict__ b, int layer) {
    int idx = blockIdx.x * 256 + threadIdx.x;
    if (idx < 2 * KT * NG) {
        int k = idx >> 12;        // row 0..2047
        int p = idx & 4095;       // packed column
        int u = p >> 2, g = p & 3;
        float v  = W[(size_t)k * NG + g * HH + u];
        float hi = to_tf32(v);
        float lo = v - hi;
        if (k < KT) {
            g_Wxp[layer][(size_t)k * NG + p] = hi;
            g_Wxr[layer][(size_t)k * NG + p] = to_tf32(lo);
        } else {
            int kk = k - KT;
            int n0b = p >> 5, c = p & 31;
            int wn = c >> 4, nt = (c >> 3) & 1, gg = c & 7;
            int kt = kk >> 5, kr = kk & 31;
            int ks = kr >> 3, tr = kr & 7;
            int r = tr >> 2, tg = tr & 3;
            int lane = gg * 4 + tg;
            int f = ((ks * 2 + nt) * 2 + wn) * 64 + lane * 2 + r;
            g_Whf[layer][(size_t)n0b * 32768 + kt * 1024 + f] = hi;
            g_Whr[layer][(size_t)n0b * 32768 + kt * 1024 + f] = __float2bfloat16(lo);
        }
    }
    if (idx < NG) {
        int u = idx >> 2, g = idx & 3;
        g_bp[layer][idx] = b[g * HH + u];
    }
}

// ---------------------------------------------------------------------------
// Pre-GEMM with 3-MMA split, cp.async double-buffered pipeline.
// Block tile 64(M) x 128(N), BK=32, 256 threads (8 warps: 4m x 2n).
// Dynamic smem: 2 x (A 2304 + Whi 4224 + Wlo 4224) floats = 86016 B -> 2 CTAs/SM.
// ---------------------------------------------------------------------------
#define PG_A  2304            // 64*36
#define PG_W  4224            // 32*132
#define PGSMEM_BYTES ((2 * PG_A + 4 * PG_W) * 4)

__global__ __launch_bounds__(256, 2)
void pregemm_kernel(const float* __restrict__ x, int layer) {
    extern __shared__ float psm[];
    float* a_b = psm;                       // [2][PG_A]
    float* w_b = psm + 2 * PG_A;            // [2][PG_W] hi
    float* r_b = psm + 2 * PG_A + 2 * PG_W; // [2][PG_W] lo

    const float* __restrict__ A   = layer ? g_y0 : x;
    const float* __restrict__ Wp  = g_Wxp[layer];
    const float* __restrict__ Wr  = g_Wxr[layer];

    int tid = threadIdx.x, warp = tid >> 5, lane = tid & 31;
    int wm = warp & 3, wn = warp >> 2;
    int gg = lane >> 2, tg = lane & 3;
    size_t m0 = (size_t)blockIdx.y * 64;
    int n0 = blockIdx.x * 128;

    float acc[32];
#pragma unroll
    for (int i = 0; i < 32; i++) acc[i] = 0.f;

    auto load_stage = [&](int kt, int s) {
        float* a_s = a_b + s * PG_A;
        float* w_s = w_b + s * PG_W;
        float* w_r = r_b + s * PG_W;
#pragma unroll
        for (int r = 0; r < 2; r++) {                  // A 64x32 raw fp32
            int q = tid + (r << 8);
            int row = q >> 3, c = (q & 7) << 2;
            cp16(a_s + row * 36 + c, A + (m0 + row) * KT + kt + c);
        }
#pragma unroll
        for (int r = 0; r < 4; r++) {                  // W hi + lo 32x128
            int q = tid + (r << 8);
            int row = q >> 5, c = (q & 31) << 2;
            cp16(w_s + row * 132 + c, Wp + (size_t)(kt + row) * NG + n0 + c);
            cp16(w_r + row * 132 + c, Wr + (size_t)(kt + row) * NG + n0 + c);
        }
        asm volatile("cp.async.commit_group;\n");
    };

    load_stage(0, 0);
    int buf = 0;
    for (int ktile = 0; ktile < 32; ktile++) {
        if (ktile < 31) {
            load_stage((ktile + 1) * 32, buf ^ 1);
            asm volatile("cp.async.wait_group 1;\n");
        } else {
            asm volatile("cp.async.wait_group 0;\n");
        }
        __syncthreads();

        const float* a_s = a_b + buf * PG_A;
        const float* w_s = w_b + buf * PG_W;
        const float* w_r = r_b + buf * PG_W;
#pragma unroll
        for (int ks = 0; ks < 4; ks++) {
            int k0 = ks * 8;
            int ar = wm * 16 + gg;
            float v0 = a_s[ar * 36 + k0 + tg];
            float v1 = a_s[(ar + 8) * 36 + k0 + tg];
            float v2 = a_s[ar * 36 + k0 + tg + 4];
            float v3 = a_s[(ar + 8) * 36 + k0 + tg + 4];
            float h0 = to_tf32(v0), h1 = to_tf32(v1), h2 = to_tf32(v2), h3 = to_tf32(v3);
            uint32_t af_hi[4] = { __float_as_uint(h0), __float_as_uint(h1),
                                  __float_as_uint(h2), __float_as_uint(h3) };
            uint32_t af_lo[4] = { __float_as_uint(to_tf32(v0 - h0)),
                                  __float_as_uint(to_tf32(v1 - h1)),
                                  __float_as_uint(to_tf32(v2 - h2)),
                                  __float_as_uint(to_tf32(v3 - h3)) };
#pragma unroll
            for (int nt = 0; nt < 8; nt++) {
                int bc = wn * 64 + nt * 8 + gg;
                uint32_t bf_hi[2] = { __float_as_uint(w_s[(k0 + tg) * 132 + bc]),
                                      __float_as_uint(w_s[(k0 + tg + 4) * 132 + bc]) };
                uint32_t bf_lo[2] = { __float_as_uint(w_r[(k0 + tg) * 132 + bc]),
                                      __float_as_uint(w_r[(k0 + tg + 4) * 132 + bc]) };
                mma8(acc + nt * 4, af_hi, bf_hi);
                mma8(acc + nt * 4, af_hi, bf_lo);
                mma8(acc + nt * 4, af_lo, bf_hi);
            }
        }
        __syncthreads();
        buf ^= 1;
    }

#pragma unroll
    for (int nt = 0; nt < 8; nt++) {
        int col = n0 + wn * 64 + nt * 8 + 2 * tg;
        size_t row = m0 + wm * 16 + gg;
        float bv0 = g_bp[layer][col], bv1 = g_bp[layer][col + 1];
        g_Z[row * NG + col]           = acc[nt * 4 + 0] + bv0;
        g_Z[row * NG + col + 1]       = acc[nt * 4 + 1] + bv1;
        g_Z[(row + 8) * NG + col]     = acc[nt * 4 + 2] + bv0;
        g_Z[(row + 8) * NG + col + 1] = acc[nt * 4 + 3] + bv1;
    }
}

// ---------------------------------------------------------------------------
// Persistent recurrent kernel, 3-MMA split precision.
// Smem: W hi 128KB + W lo (bf16) 64KB + h double buffer 18KB = 215KB.
// ---------------------------------------------------------------------------
#define SMEM_WF 32768
#define SMEM_WL 16384                 // 32768 bf16 in float-slot units
#define HSTRIDE 36
#define HBUF (64 * HSTRIDE)
#define RSMEM_BYTES ((SMEM_WF + SMEM_WL + 2 * HBUF) * 4)

__global__ __launch_bounds__(256, 1)
void recurrent_kernel(int layer, float* __restrict__ dout) {
    extern __shared__ float sm[];
    float* Wf = sm;                                    // hi, fragment-major
    __nv_bfloat16* Wl = (__nv_bfloat16*)(sm + SMEM_WF);// lo, same indexing
    float* h_s0 = sm + SMEM_WF + SMEM_WL;
    float* h_s1 = sm + SMEM_WF + SMEM_WL + HBUF;
    float* zs   = h_s0;   // epilogue staging reuses buffer 0

    const float* __restrict__ Wsrc = g_Whf[layer] + (size_t)blockIdx.x * SMEM_WF;
    const __nv_bfloat16* __restrict__ Wlsrc = g_Whr[layer] + (size_t)blockIdx.x * SMEM_WF;
    float* __restrict__ cbuf = g_cS[layer];
    float* __restrict__ yout = layer ? dout : g_y0;

    int tid = threadIdx.x, warp = tid >> 5, lane = tid & 31;
    int wm = warp & 3, wn = warp >> 2;
    int gg = lane >> 2, tg = lane & 3;
    int n0 = blockIdx.x * 32;

    // One-time W slice load: hi 128KB + lo 64KB
    for (int i = tid * 4; i < SMEM_WF; i += 1024) cp16(&Wf[i], Wsrc + i);
    for (int i = tid * 8; i < 2 * SMEM_WL; i += 2048) cp16(&Wl[i], Wlsrc + i);
    asm volatile("cp.async.commit_group;\n");

    int lb0 = g_len[tid >> 3];
    int lb1 = g_len[32 + (tid >> 3)];

    for (int t = 0; t < TT; t++) {
        const float* __restrict__ hin  = (t & 1) ? g_hB[layer] : g_hA[layer];
        float* __restrict__       hout = (t & 1) ? g_hA[layer] : g_hB[layer];

        float acc[8];
#pragma unroll
        for (int i = 0; i < 8; i++) acc[i] = 0.f;

        // first h tile
        {
#pragma unroll
            for (int rr = 0; rr < 2; rr++) {
                int q = tid + (rr << 8);
                int row = q >> 3, c = (q & 7) << 2;
                cp16(&h_s0[row * HSTRIDE + c], hin + (size_t)row * HH + c);
            }
            asm volatile("cp.async.commit_group;\n");
        }

#pragma unroll 2
        for (int ktile = 0; ktile < 32; ktile++) {
            float* cb = (ktile & 1) ? h_s1 : h_s0;
            float* nb = (ktile & 1) ? h_s0 : h_s1;
            if (ktile < 31) {
                int kt = (ktile + 1) * 32;
#pragma unroll
                for (int rr = 0; rr < 2; rr++) {
                    int q = tid + (rr << 8);
                    int row = q >> 3, c = (q & 7) << 2;
                    cp16(&nb[row * HSTRIDE + c], hin + (size_t)row * HH + kt + c);
                }
                asm volatile("cp.async.commit_group;\n");
                asm volatile("cp.async.wait_group 1;\n");
            } else {
                asm volatile("cp.async.wait_group 0;\n");
            }
            __syncthreads();

            int fb = ktile * 1024 + wn * 64 + lane * 2;
#pragma unroll
            for (int ks = 0; ks < 4; ks++) {
                int k0 = ks * 8;
                int ar = wm * 16 + gg;
                float v0 = cb[ar * HSTRIDE + k0 + tg];
                float v1 = cb[(ar + 8) * HSTRIDE + k0 + tg];
                float v2 = cb[ar * HSTRIDE + k0 + tg + 4];
                float v3 = cb[(ar + 8) * HSTRIDE + k0 + tg + 4];
                float h0 = to_tf32(v0), h1 = to_tf32(v1), h2 = to_tf32(v2), h3 = to_tf32(v3);
                uint32_t af_hi[4] = { __float_as_uint(h0), __float_as_uint(h1),
                                      __float_as_uint(h2), __float_as_uint(h3) };
                uint32_t af_lo[4] = { __float_as_uint(to_tf32(v0 - h0)),
                                      __float_as_uint(to_tf32(v1 - h1)),
                                      __float_as_uint(to_tf32(v2 - h2)),
                                      __float_as_uint(to_tf32(v3 - h3)) };
#pragma unroll
                for (int nt = 0; nt < 2; nt++) {
                    int fi = fb + (ks * 2 + nt) * 128;
                    float2 whi = *(const float2*)(Wf + fi);
                    float2 wlo = __bfloat1622float2(*(const __nv_bfloat162*)(Wl + fi));
                    uint32_t bf_hi[2] = { __float_as_uint(whi.x), __float_as_uint(whi.y) };
                    uint32_t bf_lo[2] = { __float_as_uint(wlo.x), __float_as_uint(wlo.y) };
                    mma8(acc + nt * 4, af_hi, bf_hi);
                    mma8(acc + nt * 4, af_hi, bf_lo);
                    mma8(acc + nt * 4, af_lo, bf_hi);
                }
            }
            __syncthreads();
        }

        // Stage accumulators so each thread can gather full (i,j,f,o)
#pragma unroll
        for (int nt = 0; nt < 2; nt++) {
            int col = wn * 16 + nt * 8 + 2 * tg;
            int row = wm * 16 + gg;
            zs[row * 32 + col]           = acc[nt * 4 + 0];
            zs[row * 32 + col + 1]       = acc[nt * 4 + 1];
            zs[(row + 8) * 32 + col]     = acc[nt * 4 + 2];
            zs[(row + 8) * 32 + col + 1] = acc[nt * 4 + 3];
        }
        __syncthreads();

        // Fused gate epilogue: 512 (b, unit) items / 256 threads
#pragma unroll
        for (int rr = 0; rr < 2; rr++) {
            int it = tid + (rr << 8);
            int b = it >> 3, u = it & 7;
            int uglob = (n0 >> 2) + u;
            float4 zp = *(const float4*)(g_Z + ((size_t)b * TT + t) * NG + n0 + u * 4);
            float zi = zs[b * 32 + u * 4 + 0] + zp.x;
            float zj = zs[b * 32 + u * 4 + 1] + zp.y;
            float zf = zs[b * 32 + u * 4 + 2] + zp.z;
            float zo = zs[b * 32 + u * 4 + 3] + zp.w;

            float co = cbuf[b * HH + uglob];
            float ho = hin[b * HH + uglob];

            float ig = sigm(zi);
            float fg = sigm(zf + 1.0f);     // FORGET_BIAS
            float og = sigm(zo);
            float cn = co * fg + ig * tanhf(zj);
            float hn = tanhf(cn) * og;

            int lb = rr ? lb1 : lb0;
            bool m = t < lb;
            cbuf[b * HH + uglob] = m ? cn : co;
            hout[b * HH + uglob] = m ? hn : ho;
            yout[((size_t)b * TT + t) * HH + uglob] = m ? hn : 0.f;
        }

        grid_barrier();
    }
}

// ---------------------------------------------------------------------------
// Copy final h/c stacks into d_out after y1. T=512 even -> final h lives in g_hA.
// ---------------------------------------------------------------------------
__global__ void finalize_kernel(float* __restrict__ dout) {
    int i = blockIdx.x * 256 + threadIdx.x;
    const size_t YN = (size_t)BB * TT * HH;
    if (i < 2 * BB * HH) {
        int layer = i >> 16;       // BB*HH = 65536 per layer
        int j = i & 65535;
        dout[YN + i]               = g_hA[layer][j];
        dout[YN + 2 * BB * HH + i] = g_cS[layer][j];
    }
}

// ---------------------------------------------------------------------------
// kernel_launch: identify inputs by element count, 8 graph nodes total.
// ---------------------------------------------------------------------------
extern "C" void kernel_launch(void* const* d_in, const int* in_sizes, int n_in,
                              void* d_out, int out_size) {
    int ix = -1, il = -1, iw[2] = {-1, -1}, ib[2] = {-1, -1};
    for (int i = 0; i < n_in; i++) {
        int n = in_sizes[i];
        if (n == BB * TT * DD)            { if (ix < 0) ix = i; }
        else if (n == BB)                 { if (il < 0) il = i; }
        else if (n == (DD + HH) * NG)     { if (iw[0] < 0) iw[0] = i; else if (iw[1] < 0) iw[1] = i; }
        else if (n == NG)                 { if (ib[0] < 0) ib[0] = i; else if (ib[1] < 0) ib[1] = i; }
    }
    if (ix < 0) ix = 0;
    if (il < 0) il = 1;
    if (iw[0] < 0) iw[0] = 2;
    if (ib[0] < 0) ib[0] = 3;
    if (iw[1] < 0) iw[1] = 4;
    if (ib[1] < 0) ib[1] = 5;

    const float*     x    = (const float*)d_in[ix];
    const long long* lens = (const long long*)d_in[il];
    const float*     W0   = (const float*)d_in[iw[0]];
    const float*     b0   = (const float*)d_in[ib[0]];
    const float*     W1   = (const float*)d_in[iw[1]];
    const float*     b1   = (const float*)d_in[ib[1]];
    float*           out  = (float*)d_out;

    cudaFuncSetAttribute(recurrent_kernel,
                         cudaFuncAttributeMaxDynamicSharedMemorySize, RSMEM_BYTES);
    cudaFuncSetAttribute(pregemm_kernel,
                         cudaFuncAttributeMaxDynamicSharedMemorySize, PGSMEM_BYTES);

    setup_kernel<<<256, 256>>>(lens);
    pack_kernel<<<32768, 256>>>(W0, b0, 0);
    pack_kernel<<<32768, 256>>>(W1, b1, 1);

    pregemm_kernel<<<dim3(32, 512), 256, PGSMEM_BYTES>>>(x, 0);
    recurrent_kernel<<<NBLK, 256, RSMEM_BYTES>>>(0, out);

    pregemm_kernel<<<dim3(32, 512), 256, PGSMEM_BYTES>>>(x, 1);
    recurrent_kernel<<<NBLK, 256, RSMEM_BYTES>>>(1, out);

    finalize_kernel<<<512, 256>>>(out);
}

// round 8
// speedup vs baseline: 1.0832x; 1.0408x over previous
#include <cuda_runtime.h>
#include <cuda_bf16.h>
#include <cstdint>

// Problem constants
#define BB 64
#define TT 512
#define DD 1024
#define HH 1024
#define NG 4096   // 4*H
#define KT 1024   // K depth of every GEMM (D == H == 1024)
#define NBLK 128  // CTAs in recurrent kernel (each owns 32 packed gate cols)

// ---------------------------------------------------------------------------
// Device-global scratch (no runtime allocation allowed)
// ---------------------------------------------------------------------------
__device__ float g_Z  [(size_t)BB * TT * NG];   // 512 MB: precomputed x-part of gates (packed cols)
__device__ float g_y0 [(size_t)BB * TT * HH];   // 128 MB: layer-0 outputs (layer-1 inputs)
__device__ float g_Wxp[2][(size_t)KT * NG];     // input weights hi (tf32), FRAGMENT-major
__device__ float g_Wxr[2][(size_t)KT * NG];     // input weights lo residual (tf32), same layout
__device__ float g_Whf[2][(size_t)KT * NG];     // recurrent weights hi (tf32), fragment-major
__device__ __nv_bfloat16 g_Whr[2][(size_t)KT * NG]; // recurrent weights lo residual (bf16), same idx
__device__ float g_bp [2][NG];                  // packed bias per layer
__device__ float g_hA [2][BB * HH];             // h ping
__device__ float g_hB [2][BB * HH];             // h pong
__device__ float g_cS [2][BB * HH];             // c state (CTA-exclusive cols)
__device__ int   g_len[BB];                     // normalized lengths (int32)

// Grid barrier state
__device__ volatile unsigned g_gen;
__device__ unsigned g_count;

// ---------------------------------------------------------------------------
// Helpers
// ---------------------------------------------------------------------------
__device__ __forceinline__ float to_tf32(float x) {
    float r;
    asm("cvt.rna.tf32.f32 %0, %1;" : "=f"(r) : "f"(x));
    return r;
}

__device__ __forceinline__ void mma8(float* c, const uint32_t* a, const uint32_t* b) {
    asm volatile(
        "mma.sync.aligned.m16n8k8.row.col.f32.tf32.tf32.f32 "
        "{%0,%1,%2,%3},{%4,%5,%6,%7},{%8,%9},{%0,%1,%2,%3};\n"
        : "+f"(c[0]), "+f"(c[1]), "+f"(c[2]), "+f"(c[3])
        : "r"(a[0]), "r"(a[1]), "r"(a[2]), "r"(a[3]), "r"(b[0]), "r"(b[1]));
}

__device__ __forceinline__ void cp16(void* smem_dst, const void* gmem_src) {
    unsigned s = (unsigned)__cvta_generic_to_shared(smem_dst);
    asm volatile("cp.async.cg.shared.global [%0], [%1], 16;\n" :: "r"(s), "l"(gmem_src));
}

__device__ __forceinline__ float sigm(float x) { return 1.0f / (1.0f + __expf(-x)); }

// ---------------------------------------------------------------------------
// Setup: lengths normalization (int64/int32 autodetect) + state/barrier init.
// ---------------------------------------------------------------------------
__global__ void setup_kernel(const long long* __restrict__ l64) {
    int i = blockIdx.x * 256 + threadIdx.x;
    if (i == 0) { g_gen = 0; g_count = 0; }
    if (i < BB * HH) {
        g_hA[0][i] = 0.f; g_hA[1][i] = 0.f;
        g_cS[0][i] = 0.f; g_cS[1][i] = 0.f;
    }
    if (blockIdx.x == 0 && threadIdx.x < BB) {
        const int* l32 = (const int*)l64;
        __shared__ int bad;
        if (threadIdx.x == 0) bad = 0;
        __syncwarp(0xFFFFFFFF);
        if (threadIdx.x < 32) {
            long long v = l64[threadIdx.x];
            if (v < 1 || v > TT) atomicOr(&bad, 1);
        }
        __syncthreads();
        int L = bad ? l32[threadIdx.x] : (int)l64[threadIdx.x];
        g_len[threadIdx.x] = L;
    }
}

// Pad node so the ncu capture window (-s 5 -c 1) lands on recurrent_kernel.
__global__ void pad_kernel() {}

// ---------------------------------------------------------------------------
// Weight packing with hi/lo precision split. Both halves fragment-major.
//
// Wx (k<KT): n-block nb = 128 cols; within 32x128 k-tile:
//   f = (ks*8+nt)*128 + wn*64 + (gg*4+tg)*2 + r
//   value at row kt*32 + ks*8 + tg + 4r, col nb*128 + wn*64 + nt*8 + gg
//   dest: nb*131072 + kt*4096 + f   (hi tf32 -> g_Wxp, lo tf32 -> g_Wxr)
//
// Wh (k>=KT): per-CTA 32-col slice, as before:
//   f = (ks*2+nt)*128 + wn*64 + lane*2 + r ; dest n0b*32768 + kt*1024 + f
//   (hi tf32 -> g_Whf, lo bf16 -> g_Whr)
// ---------------------------------------------------------------------------
__global__ void pack_kernel(const float* __restrict__ W, const float* __restrict__ b, int layer) {
    int idx = blockIdx.x * 256 + threadIdx.x;
    if (idx < 2 * KT * NG) {
        int k = idx >> 12;        // row 0..2047
        int p = idx & 4095;       // packed column (u*4+g)
        int u = p >> 2, g = p & 3;
        float v  = W[(size_t)k * NG + g * HH + u];
        float hi = to_tf32(v);
        float lo = v - hi;
        if (k < KT) {
            int nb = p >> 7, c = p & 127;
            int wn = c >> 6, cc = c & 63, nt = cc >> 3, gg = cc & 7;
            int kt = k >> 5, kr = k & 31;
            int ks = kr >> 3, tr = kr & 7;
            int r = tr >> 2, tg = tr & 3;
            int f = (ks * 8 + nt) * 128 + wn * 64 + (gg * 4 + tg) * 2 + r;
            size_t d = (size_t)nb * 131072 + kt * 4096 + f;
            g_Wxp[layer][d] = hi;
            g_Wxr[layer][d] = to_tf32(lo);
        } else {
            int kk = k - KT;
            int n0b = p >> 5, c = p & 31;
            int wn = c >> 4, nt = (c >> 3) & 1, gg = c & 7;
            int kt = kk >> 5, kr = kk & 31;
            int ks = kr >> 3, tr = kr & 7;
            int r = tr >> 2, tg = tr & 3;
            int f = (ks * 2 + nt) * 128 + wn * 64 + (gg * 4 + tg) * 2 + r;
            size_t d = (size_t)n0b * 32768 + kt * 1024 + f;
            g_Whf[layer][d] = hi;
            g_Whr[layer][d] = __float2bfloat16(lo);
        }
    }
    if (idx < NG) {
        int u = idx >> 2, g = idx & 3;
        g_bp[layer][idx] = b[g * HH + u];
    }
}

// ---------------------------------------------------------------------------
// Pre-GEMM with 3-MMA split, cp.async double-buffered, fragment-major W.
// Block tile 64(M) x 128(N), BK=32, 256 threads (8 warps: 4m x 2n).
// Dynamic smem: 2 x (A 2304 + Whi 4096 + Wlo 4096) floats = 83968 B -> 2 CTAs/SM.
// ---------------------------------------------------------------------------
#define PG_A  2304            // 64*36
#define PG_W  4096            // fragment-major 32x128 tile
#define PGSMEM_BYTES ((2 * PG_A + 4 * PG_W) * 4)

__global__ __launch_bounds__(256, 2)
void pregemm_kernel(const float* __restrict__ x, int layer) {
    extern __shared__ float psm[];
    float* a_b = psm;                       // [2][PG_A]
    float* w_b = psm + 2 * PG_A;            // [2][PG_W] hi
    float* r_b = psm + 2 * PG_A + 2 * PG_W; // [2][PG_W] lo

    const float* __restrict__ A   = layer ? g_y0 : x;
    const float* __restrict__ Wp  = g_Wxp[layer] + (size_t)blockIdx.x * 131072;
    const float* __restrict__ Wr  = g_Wxr[layer] + (size_t)blockIdx.x * 131072;

    int tid = threadIdx.x, warp = tid >> 5, lane = tid & 31;
    int wm = warp & 3, wn = warp >> 2;
    int gg = lane >> 2, tg = lane & 3;
    size_t m0 = (size_t)blockIdx.y * 64;
    int n0 = blockIdx.x * 128;

    float acc[32];
#pragma unroll
    for (int i = 0; i < 32; i++) acc[i] = 0.f;

    auto load_stage = [&](int ktile, int s) {
        float* a_s = a_b + s * PG_A;
        float* w_s = w_b + s * PG_W;
        float* w_r = r_b + s * PG_W;
        int kt = ktile * 32;
#pragma unroll
        for (int r = 0; r < 2; r++) {                  // A 64x32 raw fp32 (row-major)
            int q = tid + (r << 8);
            int row = q >> 3, c = (q & 7) << 2;
            cp16(a_s + row * 36 + c, A + (m0 + row) * KT + kt + c);
        }
#pragma unroll
        for (int r = 0; r < 4; r++) {                  // W hi + lo, linear fragment-major
            int i = tid * 4 + r * 1024;
            cp16(w_s + i, Wp + (size_t)ktile * 4096 + i);
            cp16(w_r + i, Wr + (size_t)ktile * 4096 + i);
        }
        asm volatile("cp.async.commit_group;\n");
    };

    load_stage(0, 0);
    int buf = 0;
    for (int ktile = 0; ktile < 32; ktile++) {
        if (ktile < 31) {
            load_stage(ktile + 1, buf ^ 1);
            asm volatile("cp.async.wait_group 1;\n");
        } else {
            asm volatile("cp.async.wait_group 0;\n");
        }
        __syncthreads();

        const float* a_s = a_b + buf * PG_A;
        const float* w_s = w_b + buf * PG_W;
        const float* w_r = r_b + buf * PG_W;
#pragma unroll
        for (int ks = 0; ks < 4; ks++) {
            int k0 = ks * 8;
            int ar = wm * 16 + gg;
            float v0 = a_s[ar * 36 + k0 + tg];
            float v1 = a_s[(ar + 8) * 36 + k0 + tg];
            float v2 = a_s[ar * 36 + k0 + tg + 4];
            float v3 = a_s[(ar + 8) * 36 + k0 + tg + 4];
            float h0 = to_tf32(v0), h1 = to_tf32(v1), h2 = to_tf32(v2), h3 = to_tf32(v3);
            uint32_t af_hi[4] = { __float_as_uint(h0), __float_as_uint(h1),
                                  __float_as_uint(h2), __float_as_uint(h3) };
            uint32_t af_lo[4] = { __float_as_uint(to_tf32(v0 - h0)),
                                  __float_as_uint(to_tf32(v1 - h1)),
                                  __float_as_uint(to_tf32(v2 - h2)),
                                  __float_as_uint(to_tf32(v3 - h3)) };
#pragma unroll
            for (int nt = 0; nt < 8; nt++) {
                int fi = (ks * 8 + nt) * 128 + wn * 64 + lane * 2;
                float2 whi = *(const float2*)(w_s + fi);
                float2 wlo = *(const float2*)(w_r + fi);
                uint32_t bf_hi[2] = { __float_as_uint(whi.x), __float_as_uint(whi.y) };
                uint32_t bf_lo[2] = { __float_as_uint(wlo.x), __float_as_uint(wlo.y) };
                mma8(acc + nt * 4, af_hi, bf_hi);
                mma8(acc + nt * 4, af_hi, bf_lo);
                mma8(acc + nt * 4, af_lo, bf_hi);
            }
        }
        __syncthreads();
        buf ^= 1;
    }

#pragma unroll
    for (int nt = 0; nt < 8; nt++) {
        int col = n0 + wn * 64 + nt * 8 + 2 * tg;
        size_t row = m0 + wm * 16 + gg;
        float bv0 = g_bp[layer][col], bv1 = g_bp[layer][col + 1];
        g_Z[row * NG + col]           = acc[nt * 4 + 0] + bv0;
        g_Z[row * NG + col + 1]       = acc[nt * 4 + 1] + bv1;
        g_Z[(row + 8) * NG + col]     = acc[nt * 4 + 2] + bv0;
        g_Z[(row + 8) * NG + col + 1] = acc[nt * 4 + 3] + bv1;
    }
}

// ---------------------------------------------------------------------------
// Persistent recurrent kernel, 3-MMA split precision.
// 3-stage h pipeline, ONE __syncthreads per k-tile, split grid barrier.
// Smem: W hi 128KB + W lo (bf16) 64KB + h triple buffer 27KB = 219KB.
// ---------------------------------------------------------------------------
#define SMEM_WF 32768
#define SMEM_WL 16384                 // 32768 bf16 in float-slot units
#define HSTRIDE 36
#define HBUF (64 * HSTRIDE)
#define RSMEM_BYTES ((SMEM_WF + SMEM_WL + 3 * HBUF) * 4)

__global__ __launch_bounds__(256, 1)
void recurrent_kernel(int layer, float* __restrict__ dout) {
    extern __shared__ float sm[];
    float* Wf = sm;                                    // hi, fragment-major
    __nv_bfloat16* Wl = (__nv_bfloat16*)(sm + SMEM_WF);// lo, same indexing
    float* hst0 = sm + SMEM_WF + SMEM_WL;              // 3 h stages
    float* zs   = hst0;   // epilogue staging reuses stage 0 (safe: holds tile 30)

    const float* __restrict__ Wsrc = g_Whf[layer] + (size_t)blockIdx.x * SMEM_WF;
    const __nv_bfloat16* __restrict__ Wlsrc = g_Whr[layer] + (size_t)blockIdx.x * SMEM_WF;
    float* __restrict__ cbuf = g_cS[layer];
    float* __restrict__ yout = layer ? dout : g_y0;

    int tid = threadIdx.x, warp = tid >> 5, lane = tid & 31;
    int wm = warp & 3, wn = warp >> 2;
    int gg = lane >> 2, tg = lane & 3;
    int n0 = blockIdx.x * 32;

    // One-time W slice load: hi 128KB + lo 64KB
    for (int i = tid * 4; i < SMEM_WF; i += 1024) cp16(&Wf[i], Wsrc + i);
    for (int i = tid * 8; i < 2 * SMEM_WL; i += 2048) cp16(&Wl[i], Wlsrc + i);
    asm volatile("cp.async.commit_group;\n");

    int lb0 = g_len[tid >> 3];
    int lb1 = g_len[32 + (tid >> 3)];

    for (int t = 0; t < TT; t++) {
        const float* __restrict__ hin  = (t & 1) ? g_hB[layer] : g_hA[layer];
        float* __restrict__       hout = (t & 1) ? g_hA[layer] : g_hB[layer];

        float acc[8];
#pragma unroll
        for (int i = 0; i < 8; i++) acc[i] = 0.f;

        // prologue: stage tiles 0 and 1
#pragma unroll
        for (int p = 0; p < 2; p++) {
            float* dst = hst0 + p * HBUF;
#pragma unroll
            for (int rr = 0; rr < 2; rr++) {
                int q = tid + (rr << 8);
                int row = q >> 3, c = (q & 7) << 2;
                cp16(dst + row * HSTRIDE + c, hin + (size_t)row * HH + p * 32 + c);
            }
            asm volatile("cp.async.commit_group;\n");
        }

        int cur = 0;                 // slot of tile i
        for (int i = 0; i < 32; i++) {
            if (i < 31) asm volatile("cp.async.wait_group 1;\n");
            else        asm volatile("cp.async.wait_group 0;\n");
            __syncthreads();          // tile i ready AND compute(i-1) done everywhere

            if (i < 30) {             // prefetch tile i+2 into slot (cur+2)%3
                int ls = cur + 2; if (ls >= 3) ls -= 3;
                float* dst = hst0 + ls * HBUF;
                int kt = (i + 2) * 32;
#pragma unroll
                for (int rr = 0; rr < 2; rr++) {
                    int q = tid + (rr << 8);
                    int row = q >> 3, c = (q & 7) << 2;
                    cp16(dst + row * HSTRIDE + c, hin + (size_t)row * HH + kt + c);
                }
                asm volatile("cp.async.commit_group;\n");
            }

            const float* cb = hst0 + cur * HBUF;
            int fb = i * 1024 + wn * 64 + lane * 2;
#pragma unroll
            for (int ks = 0; ks < 4; ks++) {
                int k0 = ks * 8;
                int ar = wm * 16 + gg;
                float v0 = cb[ar * HSTRIDE + k0 + tg];
                float v1 = cb[(ar + 8) * HSTRIDE + k0 + tg];
                float v2 = cb[ar * HSTRIDE + k0 + tg + 4];
                float v3 = cb[(ar + 8) * HSTRIDE + k0 + tg + 4];
                float h0 = to_tf32(v0), h1 = to_tf32(v1), h2 = to_tf32(v2), h3 = to_tf32(v3);
                uint32_t af_hi[4] = { __float_as_uint(h0), __float_as_uint(h1),
                                      __float_as_uint(h2), __float_as_uint(h3) };
                uint32_t af_lo[4] = { __float_as_uint(to_tf32(v0 - h0)),
                                      __float_as_uint(to_tf32(v1 - h1)),
                                      __float_as_uint(to_tf32(v2 - h2)),
                                      __float_as_uint(to_tf32(v3 - h3)) };
#pragma unroll
                for (int nt = 0; nt < 2; nt++) {
                    int fi = fb + (ks * 2 + nt) * 128;
                    float2 whi = *(const float2*)(Wf + fi);
                    float2 wlo = __bfloat1622float2(*(const __nv_bfloat162*)(Wl + fi));
                    uint32_t bf_hi[2] = { __float_as_uint(whi.x), __float_as_uint(whi.y) };
                    uint32_t bf_lo[2] = { __float_as_uint(wlo.x), __float_as_uint(wlo.y) };
                    mma8(acc + nt * 4, af_hi, bf_hi);
                    mma8(acc + nt * 4, af_hi, bf_lo);
                    mma8(acc + nt * 4, af_lo, bf_hi);
                }
            }
            if (++cur == 3) cur = 0;
        }

        // Stage accumulators (slot 0 = tile 30, no longer read) so each thread
        // can gather full (i,j,f,o)
#pragma unroll
        for (int nt = 0; nt < 2; nt++) {
            int col = wn * 16 + nt * 8 + 2 * tg;
            int row = wm * 16 + gg;
            zs[row * 32 + col]           = acc[nt * 4 + 0];
            zs[row * 32 + col + 1]       = acc[nt * 4 + 1];
            zs[(row + 8) * 32 + col]     = acc[nt * 4 + 2];
            zs[(row + 8) * 32 + col + 1] = acc[nt * 4 + 3];
        }
        __syncthreads();

        // Fused gate epilogue: compute + store h first, overlap c/y with barrier
        float csel[2], ysel[2];
#pragma unroll
        for (int rr = 0; rr < 2; rr++) {
            int it = tid + (rr << 8);
            int b = it >> 3, u = it & 7;
            int uglob = (n0 >> 2) + u;
            float4 zp = *(const float4*)(g_Z + ((size_t)b * TT + t) * NG + n0 + u * 4);
            float zi = zs[b * 32 + u * 4 + 0] + zp.x;
            float zj = zs[b * 32 + u * 4 + 1] + zp.y;
            float zf = zs[b * 32 + u * 4 + 2] + zp.z;
            float zo = zs[b * 32 + u * 4 + 3] + zp.w;

            float co = cbuf[b * HH + uglob];
            float ho = hin[b * HH + uglob];

            float ig = sigm(zi);
            float fg = sigm(zf + 1.0f);     // FORGET_BIAS
            float og = sigm(zo);
            float cn = co * fg + ig * tanhf(zj);
            float hn = tanhf(cn) * og;

            int lb = rr ? lb1 : lb0;
            bool m = t < lb;
            hout[b * HH + uglob] = m ? hn : ho;   // cross-CTA data: store before arrive
            csel[rr] = m ? cn : co;
            ysel[rr] = m ? hn : 0.f;
        }

        // Split grid barrier: arrive, overlap private c/y stores, then wait.
        unsigned e = (unsigned)(layer * TT + t);
        __threadfence();
        __syncthreads();
        if (tid == 0) {
            if (atomicInc(&g_count, NBLK - 1) == NBLK - 1) g_gen = e + 1;
        }
#pragma unroll
        for (int rr = 0; rr < 2; rr++) {
            int it = tid + (rr << 8);
            int b = it >> 3, u = it & 7;
            int uglob = (n0 >> 2) + u;
            cbuf[b * HH + uglob] = csel[rr];
            yout[((size_t)b * TT + t) * HH + uglob] = ysel[rr];
        }
        if (tid == 0) {
            while (g_gen <= e) __nanosleep(64);
        }
        __threadfence();
        __syncthreads();
    }
}

// ---------------------------------------------------------------------------
// Copy final h/c stacks into d_out after y1. T=512 even -> final h lives in g_hA.
// ---------------------------------------------------------------------------
__global__ void finalize_kernel(float* __restrict__ dout) {
    int i = blockIdx.x * 256 + threadIdx.x;
    const size_t YN = (size_t)BB * TT * HH;
    if (i < 2 * BB * HH) {
        int layer = i >> 16;       // BB*HH = 65536 per layer
        int j = i & 65535;
        dout[YN + i]               = g_hA[layer][j];
        dout[YN + 2 * BB * HH + i] = g_cS[layer][j];
    }
}

// ---------------------------------------------------------------------------
// kernel_launch: identify inputs by element count, 9 graph nodes total.
// ---------------------------------------------------------------------------
extern "C" void kernel_launch(void* const* d_in, const int* in_sizes, int n_in,
                              void* d_out, int out_size) {
    int ix = -1, il = -1, iw[2] = {-1, -1}, ib[2] = {-1, -1};
    for (int i = 0; i < n_in; i++) {
        int n = in_sizes[i];
        if (n == BB * TT * DD)            { if (ix < 0) ix = i; }
        else if (n == BB)                 { if (il < 0) il = i; }
        else if (n == (DD + HH) * NG)     { if (iw[0] < 0) iw[0] = i; else if (iw[1] < 0) iw[1] = i; }
        else if (n == NG)                 { if (ib[0] < 0) ib[0] = i; else if (ib[1] < 0) ib[1] = i; }
    }
    if (ix < 0) ix = 0;
    if (il < 0) il = 1;
    if (iw[0] < 0) iw[0] = 2;
    if (ib[0] < 0) ib[0] = 3;
    if (iw[1] < 0) iw[1] = 4;
    if (ib[1] < 0) ib[1] = 5;

    const float*     x    = (const float*)d_in[ix];
    const long long* lens = (const long long*)d_in[il];
    const float*     W0   = (const float*)d_in[iw[0]];
    const float*     b0   = (const float*)d_in[ib[0]];
    const float*     W1   = (const float*)d_in[iw[1]];
    const float*     b1   = (const float*)d_in[ib[1]];
    float*           out  = (float*)d_out;

    cudaFuncSetAttribute(recurrent_kernel,
                         cudaFuncAttributeMaxDynamicSharedMemorySize, RSMEM_BYTES);
    cudaFuncSetAttribute(pregemm_kernel,
                         cudaFuncAttributeMaxDynamicSharedMemorySize, PGSMEM_BYTES);

    setup_kernel<<<256, 256>>>(lens);                       // launch 1
    pack_kernel<<<32768, 256>>>(W0, b0, 0);                 // launch 2
    pack_kernel<<<32768, 256>>>(W1, b1, 1);                 // launch 3
    pad_kernel<<<1, 32>>>();                                // launch 4 (profiler alignment)

    pregemm_kernel<<<dim3(32, 512), 256, PGSMEM_BYTES>>>(x, 0);   // launch 5
    recurrent_kernel<<<NBLK, 256, RSMEM_BYTES>>>(0, out);         // launch 6 <- ncu capture

    pregemm_kernel<<<dim3(32, 512), 256, PGSMEM_BYTES>>>(x, 1);
    recurrent_kernel<<<NBLK, 256, RSMEM_BYTES>>>(1, out);

    finalize_kernel<<<512, 256>>>(out);
}

// round 9
// speedup vs baseline: 1.4995x; 1.3843x over previous
#include <cuda_runtime.h>
#include <cuda_bf16.h>
#include <cstdint>

// Problem constants
#define BB 64
#define TT 512
#define DD 1024
#define HH 1024
#define NG 4096   // 4*H
#define KT 1024   // K depth of every GEMM (D == H == 1024)
#define NBLK 128  // CTAs in recurrent kernel (each owns 32 packed gate cols)

// ---------------------------------------------------------------------------
// Device-global scratch (no runtime allocation allowed)
// ---------------------------------------------------------------------------
__device__ float g_Z  [(size_t)BB * TT * NG];   // 512 MB: precomputed x-part of gates (packed cols)
__device__ float g_y0 [(size_t)BB * TT * HH];   // 128 MB: layer-0 outputs (layer-1 inputs)
__device__ __nv_bfloat16 g_Wx0[2][(size_t)KT * NG];  // input weights hi (bf16), fragment-major
__device__ __nv_bfloat16 g_Wx1[2][(size_t)KT * NG];  // input weights lo residual (bf16)
__device__ __nv_bfloat16 g_Wh0[2][(size_t)KT * NG];  // recurrent weights hi (bf16), fragment-major
__device__ __nv_bfloat16 g_Wh1[2][(size_t)KT * NG];  // recurrent weights lo residual (bf16)
__device__ float g_bp [2][NG];                  // packed bias per layer
__device__ float g_hA [2][BB * HH];             // h ping
__device__ float g_hB [2][BB * HH];             // h pong
__device__ float g_cS [2][BB * HH];             // c state (CTA-exclusive cols)
__device__ int   g_len[BB];                     // normalized lengths (int32)

// Grid barrier state
__device__ volatile unsigned g_gen;
__device__ unsigned g_count;

// ---------------------------------------------------------------------------
// Helpers
// ---------------------------------------------------------------------------

// m16n8k16 bf16 MMA, fp32 accumulate. C layout identical to m16n8k8.
__device__ __forceinline__ void mma16(float* c, const uint32_t* a, uint2 b) {
    asm volatile(
        "mma.sync.aligned.m16n8k16.row.col.f32.bf16.bf16.f32 "
        "{%0,%1,%2,%3},{%4,%5,%6,%7},{%8,%9},{%0,%1,%2,%3};\n"
        : "+f"(c[0]), "+f"(c[1]), "+f"(c[2]), "+f"(c[3])
        : "r"(a[0]), "r"(a[1]), "r"(a[2]), "r"(a[3]), "r"(b.x), "r"(b.y));
}

__device__ __forceinline__ void cp16(void* smem_dst, const void* gmem_src) {
    unsigned s = (unsigned)__cvta_generic_to_shared(smem_dst);
    asm volatile("cp.async.cg.shared.global [%0], [%1], 16;\n" :: "r"(s), "l"(gmem_src));
}

__device__ __forceinline__ float sigm(float x) { return 1.0f / (1.0f + __expf(-x)); }

// Split packed pair (x = k-even value, y = k-odd value) into bf16 hi + bf16 lo.
__device__ __forceinline__ void split2(float x, float y, uint32_t& hi, uint32_t& lo) {
    __nv_bfloat162 h = __floats2bfloat162_rn(x, y);
    float2 q = __bfloat1622float2(h);
    __nv_bfloat162 l = __floats2bfloat162_rn(x - q.x, y - q.y);
    hi = *reinterpret_cast<uint32_t*>(&h);
    lo = *reinterpret_cast<uint32_t*>(&l);
}

// ---------------------------------------------------------------------------
// Weight packing with bf16 hi/lo split, MMA-fragment-major (m16n8k16).
// Fragment decode for k within 16-slice: rb=kr>>3, tg=(kr&7)>>1, kb=kr&1.
// Wx (k<KT): n-block nb of 128 cols; c=wn*64+nt*8+gg.
//   bf16 idx = nb*131072 + ((((((kt*2+s)*8+nt)*2+wn)*32+lane)*2+rb)*2+kb)
// Wh (k>=KT): per-CTA 32-col slice n0b; c=wn*16+nt*8+gg.
//   bf16 idx = n0b*32768  + ((((((kt*2+s)*2+nt)*2+wn)*32+lane)*2+rb)*2+kb)
// Layer-0 launch also does lengths + state/barrier init (setup merged here).
// ---------------------------------------------------------------------------
__global__ void pack_kernel(const float* __restrict__ W, const float* __restrict__ b,
                            int layer, const long long* __restrict__ l64) {
    if (layer == 0) {
        int si = blockIdx.x * 256 + threadIdx.x;
        if (si < 4 * BB * HH) {          // zero hA[2] and cS[2]
            int which = si >> 17, l2 = (si >> 16) & 1, j = si & 65535;
            if (which == 0) g_hA[l2][j] = 0.f; else g_cS[l2][j] = 0.f;
        }
        if (blockIdx.x == 0 && threadIdx.x < BB) {
            bool bad = false;
            for (int k = 0; k < 32; k++) {
                long long v = l64[k];
                if (v < 1 || v > TT) bad = true;
            }
            int L = bad ? ((const int*)l64)[threadIdx.x] : (int)l64[threadIdx.x];
            g_len[threadIdx.x] = L;
        }
        if (blockIdx.x == 1 && threadIdx.x == 0) { g_gen = 0; g_count = 0; }
    }

    int idx = blockIdx.x * 256 + threadIdx.x;
    if (idx < 2 * KT * NG) {
        int k = idx >> 12;        // row 0..2047
        int p = idx & 4095;       // packed column (u*4+g)
        int u = p >> 2, g = p & 3;
        float v  = W[(size_t)k * NG + g * HH + u];
        __nv_bfloat16 hb = __float2bfloat16_rn(v);
        __nv_bfloat16 lb = __float2bfloat16_rn(v - __bfloat162float(hb));
        if (k < KT) {
            int nb = p >> 7, c = p & 127;
            int wn = (c >> 6) & 1, cc = c & 63, nt = cc >> 3, gg = cc & 7;
            int kt = k >> 5, krel = k & 31;
            int s = krel >> 4, kr = krel & 15;
            int rb = kr >> 3, tg = (kr & 7) >> 1, kb = kr & 1;
            int lane = gg * 4 + tg;
            size_t d = (size_t)nb * 131072 +
                       ((((((size_t)(kt * 2 + s) * 8 + nt) * 2 + wn) * 32 + lane) * 2 + rb) * 2 + kb);
            g_Wx0[layer][d] = hb;
            g_Wx1[layer][d] = lb;
        } else {
            int kk = k - KT;
            int n0b = p >> 5, c = p & 31;
            int wn = c >> 4, nt = (c >> 3) & 1, gg = c & 7;
            int kt = kk >> 5, krel = kk & 31;
            int s = krel >> 4, kr = krel & 15;
            int rb = kr >> 3, tg = (kr & 7) >> 1, kb = kr & 1;
            int lane = gg * 4 + tg;
            size_t d = (size_t)n0b * 32768 +
                       ((((((size_t)(kt * 2 + s) * 2 + nt) * 2 + wn) * 32 + lane) * 2 + rb) * 2 + kb);
            g_Wh0[layer][d] = hb;
            g_Wh1[layer][d] = lb;
        }
    }
    if (idx < NG) {
        int u = idx >> 2, g = idx & 3;
        g_bp[layer][idx] = b[g * HH + u];
    }
}

// ---------------------------------------------------------------------------
// Pre-GEMM, bf16x3 split, cp.async double-buffered, fragment-major W.
// Block tile 64(M) x 128(N), BK=32, 256 threads (8 warps: 4m x 2n).
// Dynamic smem: 2 x (A 2560 f32 + Whi 2048 u32 + Wlo 2048 u32) = 53248 B.
// ---------------------------------------------------------------------------
#define PG_A  2560            // 64*40 floats
#define PG_WU 2048            // uint32 per ktile per level
#define PGSMEM_BYTES ((2 * PG_A + 4 * PG_WU) * 4)

__global__ __launch_bounds__(256, 2)
void pregemm_kernel(const float* __restrict__ x, int layer) {
    extern __shared__ float psm[];
    float*    a_b  = psm;                                  // [2][PG_A]
    uint32_t* w0_b = (uint32_t*)(psm + 2 * PG_A);          // [2][PG_WU] hi
    uint32_t* w1_b = (uint32_t*)(psm + 2 * PG_A) + 2 * PG_WU; // [2][PG_WU] lo

    const float* __restrict__ A = layer ? g_y0 : x;
    const uint32_t* __restrict__ gW0 =
        (const uint32_t*)(g_Wx0[layer] + (size_t)blockIdx.x * 131072);
    const uint32_t* __restrict__ gW1 =
        (const uint32_t*)(g_Wx1[layer] + (size_t)blockIdx.x * 131072);

    int tid = threadIdx.x, warp = tid >> 5, lane = tid & 31;
    int wm = warp & 3, wn = warp >> 2;
    int gg = lane >> 2, tg = lane & 3;
    size_t m0 = (size_t)blockIdx.y * 64;
    int n0 = blockIdx.x * 128;

    float acc[32];
#pragma unroll
    for (int i = 0; i < 32; i++) acc[i] = 0.f;

    auto load_stage = [&](int ktile, int s) {
        float*    a_s = a_b + s * PG_A;
        uint32_t* w0s = w0_b + s * PG_WU;
        uint32_t* w1s = w1_b + s * PG_WU;
        int kt = ktile * 32;
#pragma unroll
        for (int r = 0; r < 2; r++) {                  // A 64x32 raw fp32, stride 40
            int q = tid + (r << 8);
            int row = q >> 3, c = (q & 7) << 2;
            cp16(a_s + row * 40 + c, A + (m0 + row) * KT + kt + c);
        }
#pragma unroll
        for (int r = 0; r < 2; r++) {                  // W hi + lo, linear fragment-major
            int i = tid * 4 + r * 1024;
            cp16(w0s + i, gW0 + ktile * PG_WU + i);
            cp16(w1s + i, gW1 + ktile * PG_WU + i);
        }
        asm volatile("cp.async.commit_group;\n");
    };

    load_stage(0, 0);
    int buf = 0;
    for (int ktile = 0; ktile < 32; ktile++) {
        if (ktile < 31) {
            load_stage(ktile + 1, buf ^ 1);
            asm volatile("cp.async.wait_group 1;\n");
        } else {
            asm volatile("cp.async.wait_group 0;\n");
        }
        __syncthreads();

        const float*    a_s = a_b + buf * PG_A;
        const uint2*    w0s = (const uint2*)(w0_b + buf * PG_WU);
        const uint2*    w1s = (const uint2*)(w1_b + buf * PG_WU);
        int ar = wm * 16 + gg;
#pragma unroll
        for (int s = 0; s < 2; s++) {
            int k0 = s * 16 + 2 * tg;
            float2 p0 = *(const float2*)(a_s + ar * 40 + k0);
            float2 p1 = *(const float2*)(a_s + (ar + 8) * 40 + k0);
            float2 p2 = *(const float2*)(a_s + ar * 40 + k0 + 8);
            float2 p3 = *(const float2*)(a_s + (ar + 8) * 40 + k0 + 8);
            uint32_t a_hi[4], a_lo[4];
            split2(p0.x, p0.y, a_hi[0], a_lo[0]);
            split2(p1.x, p1.y, a_hi[1], a_lo[1]);
            split2(p2.x, p2.y, a_hi[2], a_lo[2]);
            split2(p3.x, p3.y, a_hi[3], a_lo[3]);
#pragma unroll
            for (int nt = 0; nt < 8; nt++) {
                int fi = ((s * 8 + nt) * 2 + wn) * 32 + lane;
                uint2 bh = w0s[fi];
                uint2 bl = w1s[fi];
                mma16(acc + nt * 4, a_hi, bh);
                mma16(acc + nt * 4, a_hi, bl);
                mma16(acc + nt * 4, a_lo, bh);
            }
        }
        __syncthreads();
        buf ^= 1;
    }

#pragma unroll
    for (int nt = 0; nt < 8; nt++) {
        int col = n0 + wn * 64 + nt * 8 + 2 * tg;
        size_t row = m0 + wm * 16 + gg;
        float bv0 = g_bp[layer][col], bv1 = g_bp[layer][col + 1];
        g_Z[row * NG + col]           = acc[nt * 4 + 0] + bv0;
        g_Z[row * NG + col + 1]       = acc[nt * 4 + 1] + bv1;
        g_Z[(row + 8) * NG + col]     = acc[nt * 4 + 2] + bv0;
        g_Z[(row + 8) * NG + col + 1] = acc[nt * 4 + 3] + bv1;
    }
}

// ---------------------------------------------------------------------------
// Persistent recurrent kernel, bf16x3 split.
// 3-stage h pipeline, ONE __syncthreads per k-tile, split grid barrier.
// Smem: W hi 64KB + W lo 64KB + h triple buffer 30KB = 158KB.
// ---------------------------------------------------------------------------
#define RW_U 16384                    // uint32 per level per CTA
#define HSTRIDE 40
#define HBUF (64 * HSTRIDE)
#define RSMEM_BYTES ((2 * RW_U + 3 * HBUF) * 4)

__global__ __launch_bounds__(256, 1)
void recurrent_kernel(int layer, float* __restrict__ dout) {
    extern __shared__ float sm[];
    uint32_t* W0u = (uint32_t*)sm;            // hi fragments
    uint32_t* W1u = W0u + RW_U;               // lo fragments
    float* hst0 = sm + 2 * RW_U;              // 3 h stages, stride 40
    float* zs   = hst0;   // epilogue staging reuses stage 0 (holds tile 30: dead)

    const uint32_t* __restrict__ gW0 =
        (const uint32_t*)(g_Wh0[layer] + (size_t)blockIdx.x * 32768);
    const uint32_t* __restrict__ gW1 =
        (const uint32_t*)(g_Wh1[layer] + (size_t)blockIdx.x * 32768);
    float* __restrict__ cbuf = g_cS[layer];
    float* __restrict__ yout = layer ? dout : g_y0;

    int tid = threadIdx.x, warp = tid >> 5, lane = tid & 31;
    int wm = warp & 3, wn = warp >> 2;
    int gg = lane >> 2, tg = lane & 3;
    int n0 = blockIdx.x * 32;

    // One-time W slice load: 64KB hi + 64KB lo
    for (int i = tid * 4; i < RW_U; i += 1024) {
        cp16(&W0u[i], gW0 + i);
        cp16(&W1u[i], gW1 + i);
    }
    asm volatile("cp.async.commit_group;\n");

    int lb0 = g_len[tid >> 3];
    int lb1 = g_len[32 + (tid >> 3)];

    for (int t = 0; t < TT; t++) {
        const float* __restrict__ hin  = (t & 1) ? g_hB[layer] : g_hA[layer];
        float* __restrict__       hout = (t & 1) ? g_hA[layer] : g_hB[layer];

        float acc[8];
#pragma unroll
        for (int i = 0; i < 8; i++) acc[i] = 0.f;

        // prologue: stage tiles 0 and 1
#pragma unroll
        for (int p = 0; p < 2; p++) {
            float* dst = hst0 + p * HBUF;
#pragma unroll
            for (int rr = 0; rr < 2; rr++) {
                int q = tid + (rr << 8);
                int row = q >> 3, c = (q & 7) << 2;
                cp16(dst + row * HSTRIDE + c, hin + (size_t)row * HH + p * 32 + c);
            }
            asm volatile("cp.async.commit_group;\n");
        }

        int cur = 0;                 // slot of tile i
        int ar = wm * 16 + gg;
        for (int i = 0; i < 32; i++) {
            if (i < 31) asm volatile("cp.async.wait_group 1;\n");
            else        asm volatile("cp.async.wait_group 0;\n");
            __syncthreads();          // tile i ready AND compute(i-1) done everywhere

            if (i < 30) {             // prefetch tile i+2 into slot (cur+2)%3
                int ls = cur + 2; if (ls >= 3) ls -= 3;
                float* dst = hst0 + ls * HBUF;
                int kt = (i + 2) * 32;
#pragma unroll
                for (int rr = 0; rr < 2; rr++) {
                    int q = tid + (rr << 8);
                    int row = q >> 3, c = (q & 7) << 2;
                    cp16(dst + row * HSTRIDE + c, hin + (size_t)row * HH + kt + c);
                }
                asm volatile("cp.async.commit_group;\n");
            }

            const float* cb = hst0 + cur * HBUF;
#pragma unroll
            for (int s = 0; s < 2; s++) {
                int k0 = s * 16 + 2 * tg;
                float2 p0 = *(const float2*)(cb + ar * HSTRIDE + k0);
                float2 p1 = *(const float2*)(cb + (ar + 8) * HSTRIDE + k0);
                float2 p2 = *(const float2*)(cb + ar * HSTRIDE + k0 + 8);
                float2 p3 = *(const float2*)(cb + (ar + 8) * HSTRIDE + k0 + 8);
                uint32_t a_hi[4], a_lo[4];
                split2(p0.x, p0.y, a_hi[0], a_lo[0]);
                split2(p1.x, p1.y, a_hi[1], a_lo[1]);
                split2(p2.x, p2.y, a_hi[2], a_lo[2]);
                split2(p3.x, p3.y, a_hi[3], a_lo[3]);
#pragma unroll
                for (int nt = 0; nt < 2; nt++) {
                    int fi = (((i * 2 + s) * 2 + nt) * 2 + wn) * 32 + lane;
                    uint2 bh = ((const uint2*)W0u)[fi];
                    uint2 bl = ((const uint2*)W1u)[fi];
                    mma16(acc + nt * 4, a_hi, bh);
                    mma16(acc + nt * 4, a_hi, bl);
                    mma16(acc + nt * 4, a_lo, bh);
                }
            }
            if (++cur == 3) cur = 0;
        }

        // Stage accumulators (slot 0 = tile 30, dead) so each thread gathers (i,j,f,o)
#pragma unroll
        for (int nt = 0; nt < 2; nt++) {
            int col = wn * 16 + nt * 8 + 2 * tg;
            int row = wm * 16 + gg;
            zs[row * 32 + col]           = acc[nt * 4 + 0];
            zs[row * 32 + col + 1]       = acc[nt * 4 + 1];
            zs[(row + 8) * 32 + col]     = acc[nt * 4 + 2];
            zs[(row + 8) * 32 + col + 1] = acc[nt * 4 + 3];
        }
        __syncthreads();

        // Fused gate epilogue: compute + store h first, overlap c/y with barrier
        float csel[2], ysel[2];
#pragma unroll
        for (int rr = 0; rr < 2; rr++) {
            int it = tid + (rr << 8);
            int b = it >> 3, u = it & 7;
            int uglob = (n0 >> 2) + u;
            float4 zp = *(const float4*)(g_Z + ((size_t)b * TT + t) * NG + n0 + u * 4);
            float zi = zs[b * 32 + u * 4 + 0] + zp.x;
            float zj = zs[b * 32 + u * 4 + 1] + zp.y;
            float zf = zs[b * 32 + u * 4 + 2] + zp.z;
            float zo = zs[b * 32 + u * 4 + 3] + zp.w;

            float co = cbuf[b * HH + uglob];
            float ho = hin[b * HH + uglob];

            float ig = sigm(zi);
            float fg = sigm(zf + 1.0f);     // FORGET_BIAS
            float og = sigm(zo);
            float cn = co * fg + ig * tanhf(zj);
            float hn = tanhf(cn) * og;

            int lb = rr ? lb1 : lb0;
            bool m = t < lb;
            hout[b * HH + uglob] = m ? hn : ho;   // cross-CTA data: store before arrive
            csel[rr] = m ? cn : co;
            ysel[rr] = m ? hn : 0.f;
        }

        // Split grid barrier: arrive, overlap private c/y stores, then wait.
        unsigned e = (unsigned)(layer * TT + t);
        __threadfence();
        __syncthreads();
        if (tid == 0) {
            if (atomicInc(&g_count, NBLK - 1) == NBLK - 1) g_gen = e + 1;
        }
#pragma unroll
        for (int rr = 0; rr < 2; rr++) {
            int it = tid + (rr << 8);
            int b = it >> 3, u = it & 7;
            int uglob = (n0 >> 2) + u;
            cbuf[b * HH + uglob] = csel[rr];
            yout[((size_t)b * TT + t) * HH + uglob] = ysel[rr];
        }
        if (tid == 0) {
            while (g_gen <= e) __nanosleep(64);
        }
        __threadfence();
        __syncthreads();
    }
}

// ---------------------------------------------------------------------------
// Copy final h/c stacks into d_out after y1. T=512 even -> final h lives in g_hA.
// ---------------------------------------------------------------------------
__global__ void finalize_kernel(float* __restrict__ dout) {
    int i = blockIdx.x * 256 + threadIdx.x;
    const size_t YN = (size_t)BB * TT * HH;
    if (i < 2 * BB * HH) {
        int layer = i >> 16;       // BB*HH = 65536 per layer
        int j = i & 65535;
        dout[YN + i]               = g_hA[layer][j];
        dout[YN + 2 * BB * HH + i] = g_cS[layer][j];
    }
}

// ---------------------------------------------------------------------------
// kernel_launch: identify inputs by element count, 7 graph nodes.
// Node 4 = recurrent_kernel(layer 0) -> ncu capture slot.
// ---------------------------------------------------------------------------
extern "C" void kernel_launch(void* const* d_in, const int* in_sizes, int n_in,
                              void* d_out, int out_size) {
    int ix = -1, il = -1, iw[2] = {-1, -1}, ib[2] = {-1, -1};
    for (int i = 0; i < n_in; i++) {
        int n = in_sizes[i];
        if (n == BB * TT * DD)            { if (ix < 0) ix = i; }
        else if (n == BB)                 { if (il < 0) il = i; }
        else if (n == (DD + HH) * NG)     { if (iw[0] < 0) iw[0] = i; else if (iw[1] < 0) iw[1] = i; }
        else if (n == NG)                 { if (ib[0] < 0) ib[0] = i; else if (ib[1] < 0) ib[1] = i; }
    }
    if (ix < 0) ix = 0;
    if (il < 0) il = 1;
    if (iw[0] < 0) iw[0] = 2;
    if (ib[0] < 0) ib[0] = 3;
    if (iw[1] < 0) iw[1] = 4;
    if (ib[1] < 0) ib[1] = 5;

    const float*     x    = (const float*)d_in[ix];
    const long long* lens = (const long long*)d_in[il];
    const float*     W0   = (const float*)d_in[iw[0]];
    const float*     b0   = (const float*)d_in[ib[0]];
    const float*     W1   = (const float*)d_in[iw[1]];
    const float*     b1   = (const float*)d_in[ib[1]];
    float*           out  = (float*)d_out;

    cudaFuncSetAttribute(recurrent_kernel,
                         cudaFuncAttributeMaxDynamicSharedMemorySize, RSMEM_BYTES);
    cudaFuncSetAttribute(pregemm_kernel,
                         cudaFuncAttributeMaxDynamicSharedMemorySize, PGSMEM_BYTES);

    pack_kernel<<<32768, 256>>>(W0, b0, 0, lens);                 // 1 (incl. setup)
    pack_kernel<<<32768, 256>>>(W1, b1, 1, lens);                 // 2

    pregemm_kernel<<<dim3(32, 512), 256, PGSMEM_BYTES>>>(x, 0);   // 3
    recurrent_kernel<<<NBLK, 256, RSMEM_BYTES>>>(0, out);         // 4 <- ncu capture

    pregemm_kernel<<<dim3(32, 512), 256, PGSMEM_BYTES>>>(x, 1);   // 5
    recurrent_kernel<<<NBLK, 256, RSMEM_BYTES>>>(1, out);         // 6

    finalize_kernel<<<512, 256>>>(out);                           // 7
}

// round 12
// speedup vs baseline: 1.5199x; 1.0136x over previous
#include <cuda_runtime.h>
#include <cuda_bf16.h>
#include <cstdint>

// Problem constants
#define BB 64
#define TT 512
#define DD 1024
#define HH 1024
#define NG 4096   // 4*H
#define KT 1024   // K depth of every GEMM (D == H == 1024)
#define NBLK 128  // CTAs in recurrent kernel (each owns 32 packed gate cols)

// ---------------------------------------------------------------------------
// Device-global scratch (no runtime allocation allowed)
// ---------------------------------------------------------------------------
__device__ float g_Z  [(size_t)BB * TT * NG];   // 512 MB: precomputed x-part of gates (packed cols)
__device__ float g_y0 [(size_t)BB * TT * HH];   // 128 MB: layer-0 outputs (layer-1 inputs)
__device__ __nv_bfloat16 g_Wx0[2][(size_t)KT * NG];  // input weights hi (bf16), fragment-major
__device__ __nv_bfloat16 g_Wx1[2][(size_t)KT * NG];  // input weights lo residual (bf16)
__device__ __nv_bfloat16 g_Wh0[2][(size_t)KT * NG];  // recurrent weights hi (bf16), fragment-major
__device__ __nv_bfloat16 g_Wh1[2][(size_t)KT * NG];  // recurrent weights lo residual (bf16)
__device__ float g_bp [2][NG];                  // packed bias per layer
__device__ __nv_bfloat16 g_h0[2][2][BB * HH];   // h hi  [layer][pingpong]
__device__ __nv_bfloat16 g_h1[2][2][BB * HH];   // h lo
__device__ float g_cS [2][BB * HH];             // c state (CTA-exclusive cols)
__device__ int   g_len[BB];                     // normalized lengths (int32)

// Grid barrier state
__device__ volatile unsigned g_gen;
__device__ unsigned g_count;

// ---------------------------------------------------------------------------
// Helpers
// ---------------------------------------------------------------------------

// m16n8k16 bf16 MMA, fp32 accumulate. C layout identical to m16n8k8.
__device__ __forceinline__ void mma16(float* c, const uint32_t* a, uint2 b) {
    asm volatile(
        "mma.sync.aligned.m16n8k16.row.col.f32.bf16.bf16.f32 "
        "{%0,%1,%2,%3},{%4,%5,%6,%7},{%8,%9},{%0,%1,%2,%3};\n"
        : "+f"(c[0]), "+f"(c[1]), "+f"(c[2]), "+f"(c[3])
        : "r"(a[0]), "r"(a[1]), "r"(a[2]), "r"(a[3]), "r"(b.x), "r"(b.y));
}

__device__ __forceinline__ void cp16(void* smem_dst, const void* gmem_src) {
    unsigned s = (unsigned)__cvta_generic_to_shared(smem_dst);
    asm volatile("cp.async.cg.shared.global [%0], [%1], 16;\n" :: "r"(s), "l"(gmem_src));
}

__device__ __forceinline__ float sigm(float x) { return 1.0f / (1.0f + __expf(-x)); }

// Split packed pair (x = k-even value, y = k-odd value) into bf16 hi + bf16 lo.
__device__ __forceinline__ void split2(float x, float y, uint32_t& hi, uint32_t& lo) {
    __nv_bfloat162 h = __floats2bfloat162_rn(x, y);
    float2 q = __bfloat1622float2(h);
    __nv_bfloat162 l = __floats2bfloat162_rn(x - q.x, y - q.y);
    hi = *reinterpret_cast<uint32_t*>(&h);
    lo = *reinterpret_cast<uint32_t*>(&l);
}

// ---------------------------------------------------------------------------
// Weight packing with bf16 hi/lo split, MMA-fragment-major (m16n8k16).
// (unchanged from R9; validated at rel_err 1.67e-5)
// ---------------------------------------------------------------------------
__global__ void pack_kernel(const float* __restrict__ W, const float* __restrict__ b,
                            int layer, const long long* __restrict__ l64) {
    if (layer == 0) {
        int si = blockIdx.x * 256 + threadIdx.x;
        if (si < 131072) {                      // zero h hi/lo (all buffers) + cS
            ((uint32_t*)g_h0)[si] = 0u;         // 2*2*65536 bf16 = 131072 u32... (see note)
            ((uint32_t*)g_h1)[si] = 0u;
            ((float*)g_cS)[si] = 0.f;
        }
        if (blockIdx.x == 0 && threadIdx.x < BB) {
            bool bad = false;
            for (int k = 0; k < 32; k++) {
                long long v = l64[k];
                if (v < 1 || v > TT) bad = true;
            }
            int L = bad ? ((const int*)l64)[threadIdx.x] : (int)l64[threadIdx.x];
            g_len[threadIdx.x] = L;
        }
        if (blockIdx.x == 1 && threadIdx.x == 0) { g_gen = 0; g_count = 0; }
    }
    // NOTE: g_h0 holds 2*2*65536 bf16 = 262144 bf16 = 131072 u32 -> fully zeroed.

    int idx = blockIdx.x * 256 + threadIdx.x;
    if (idx < 2 * KT * NG) {
        int k = idx >> 12;        // row 0..2047
        int p = idx & 4095;       // packed column (u*4+g)
        int u = p >> 2, g = p & 3;
        float v  = W[(size_t)k * NG + g * HH + u];
        __nv_bfloat16 hb = __float2bfloat16_rn(v);
        __nv_bfloat16 lb = __float2bfloat16_rn(v - __bfloat162float(hb));
        if (k < KT) {
            int nb = p >> 7, c = p & 127;
            int wn = (c >> 6) & 1, cc = c & 63, nt = cc >> 3, gg = cc & 7;
            int kt = k >> 5, krel = k & 31;
            int s = krel >> 4, kr = krel & 15;
            int rb = kr >> 3, tg = (kr & 7) >> 1, kb = kr & 1;
            int lane = gg * 4 + tg;
            size_t d = (size_t)nb * 131072 +
                       ((((((size_t)(kt * 2 + s) * 8 + nt) * 2 + wn) * 32 + lane) * 2 + rb) * 2 + kb);
            g_Wx0[layer][d] = hb;
            g_Wx1[layer][d] = lb;
        } else {
            int kk = k - KT;
            int n0b = p >> 5, c = p & 31;
            int wn = c >> 4, nt = (c >> 3) & 1, gg = c & 7;
            int kt = kk >> 5, krel = kk & 31;
            int s = krel >> 4, kr = krel & 15;
            int rb = kr >> 3, tg = (kr & 7) >> 1, kb = kr & 1;
            int lane = gg * 4 + tg;
            size_t d = (size_t)n0b * 32768 +
                       ((((((size_t)(kt * 2 + s) * 2 + nt) * 2 + wn) * 32 + lane) * 2 + rb) * 2 + kb);
            g_Wh0[layer][d] = hb;
            g_Wh1[layer][d] = lb;
        }
    }
    if (idx < NG) {
        int u = idx >> 2, g = idx & 3;
        g_bp[layer][idx] = b[g * HH + u];
    }
}

// ---------------------------------------------------------------------------
// Pre-GEMM, bf16x3 split, cp.async double-buffered, fragment-major W.
// (unchanged from R9)
// ---------------------------------------------------------------------------
#define PG_A  2560            // 64*40 floats
#define PG_WU 2048            // uint32 per ktile per level
#define PGSMEM_BYTES ((2 * PG_A + 4 * PG_WU) * 4)

__global__ __launch_bounds__(256, 2)
void pregemm_kernel(const float* __restrict__ x, int layer) {
    extern __shared__ float psm[];
    float*    a_b  = psm;                                  // [2][PG_A]
    uint32_t* w0_b = (uint32_t*)(psm + 2 * PG_A);          // [2][PG_WU] hi
    uint32_t* w1_b = (uint32_t*)(psm + 2 * PG_A) + 2 * PG_WU; // [2][PG_WU] lo

    const float* __restrict__ A = layer ? g_y0 : x;
    const uint32_t* __restrict__ gW0 =
        (const uint32_t*)(g_Wx0[layer] + (size_t)blockIdx.x * 131072);
    const uint32_t* __restrict__ gW1 =
        (const uint32_t*)(g_Wx1[layer] + (size_t)blockIdx.x * 131072);

    int tid = threadIdx.x, warp = tid >> 5, lane = tid & 31;
    int wm = warp & 3, wn = warp >> 2;
    int gg = lane >> 2, tg = lane & 3;
    size_t m0 = (size_t)blockIdx.y * 64;
    int n0 = blockIdx.x * 128;

    float acc[32];
#pragma unroll
    for (int i = 0; i < 32; i++) acc[i] = 0.f;

    auto load_stage = [&](int ktile, int s) {
        float*    a_s = a_b + s * PG_A;
        uint32_t* w0s = w0_b + s * PG_WU;
        uint32_t* w1s = w1_b + s * PG_WU;
        int kt = ktile * 32;
#pragma unroll
        for (int r = 0; r < 2; r++) {                  // A 64x32 raw fp32, stride 40
            int q = tid + (r << 8);
            int row = q >> 3, c = (q & 7) << 2;
            cp16(a_s + row * 40 + c, A + (m0 + row) * KT + kt + c);
        }
#pragma unroll
        for (int r = 0; r < 2; r++) {                  // W hi + lo, linear fragment-major
            int i = tid * 4 + r * 1024;
            cp16(w0s + i, gW0 + ktile * PG_WU + i);
            cp16(w1s + i, gW1 + ktile * PG_WU + i);
        }
        asm volatile("cp.async.commit_group;\n");
    };

    load_stage(0, 0);
    int buf = 0;
    for (int ktile = 0; ktile < 32; ktile++) {
        if (ktile < 31) {
            load_stage(ktile + 1, buf ^ 1);
            asm volatile("cp.async.wait_group 1;\n");
        } else {
            asm volatile("cp.async.wait_group 0;\n");
        }
        __syncthreads();

        const float*    a_s = a_b + buf * PG_A;
        const uint2*    w0s = (const uint2*)(w0_b + buf * PG_WU);
        const uint2*    w1s = (const uint2*)(w1_b + buf * PG_WU);
        int ar = wm * 16 + gg;
#pragma unroll
        for (int s = 0; s < 2; s++) {
            int k0 = s * 16 + 2 * tg;
            float2 p0 = *(const float2*)(a_s + ar * 40 + k0);
            float2 p1 = *(const float2*)(a_s + (ar + 8) * 40 + k0);
            float2 p2 = *(const float2*)(a_s + ar * 40 + k0 + 8);
            float2 p3 = *(const float2*)(a_s + (ar + 8) * 40 + k0 + 8);
            uint32_t a_hi[4], a_lo[4];
            split2(p0.x, p0.y, a_hi[0], a_lo[0]);
            split2(p1.x, p1.y, a_hi[1], a_lo[1]);
            split2(p2.x, p2.y, a_hi[2], a_lo[2]);
            split2(p3.x, p3.y, a_hi[3], a_lo[3]);
#pragma unroll
            for (int nt = 0; nt < 8; nt++) {
                int fi = ((s * 8 + nt) * 2 + wn) * 32 + lane;
                uint2 bh = w0s[fi];
                uint2 bl = w1s[fi];
                mma16(acc + nt * 4, a_hi, bh);
                mma16(acc + nt * 4, a_hi, bl);
                mma16(acc + nt * 4, a_lo, bh);
            }
        }
        __syncthreads();
        buf ^= 1;
    }

#pragma unroll
    for (int nt = 0; nt < 8; nt++) {
        int col = n0 + wn * 64 + nt * 8 + 2 * tg;
        size_t row = m0 + wm * 16 + gg;
        float bv0 = g_bp[layer][col], bv1 = g_bp[layer][col + 1];
        g_Z[row * NG + col]           = acc[nt * 4 + 0] + bv0;
        g_Z[row * NG + col + 1]       = acc[nt * 4 + 1] + bv1;
        g_Z[(row + 8) * NG + col]     = acc[nt * 4 + 2] + bv0;
        g_Z[(row + 8) * NG + col + 1] = acc[nt * 4 + 3] + bv1;
    }
}

// ---------------------------------------------------------------------------
// Persistent recurrent kernel, bf16x3 split, producer-split h (hi/lo bf16).
// Paired-tile pipeline (16 syncs/step), 6 tile slots, 4x accumulator banks.
// Smem: W 128KB + h slots 6*(5KB hi + 5KB lo) = 60KB -> 188KB.
// ---------------------------------------------------------------------------
#define RW_U 16384                    // uint32 per level per CTA
#define HTS  2560                     // bf16 per h tile slot (64 rows * stride 40)
#define RSMEM_BYTES (2 * RW_U * 4 + 12 * HTS * 2)

__global__ __launch_bounds__(256, 1)
void recurrent_kernel(int layer, float* __restrict__ dout) {
    extern __shared__ float sm[];
    uint32_t* W0u = (uint32_t*)sm;            // hi fragments (64KB)
    uint32_t* W1u = W0u + RW_U;               // lo fragments (64KB)
    __nv_bfloat16* Hhi = (__nv_bfloat16*)(W1u + RW_U);   // [6][HTS]
    __nv_bfloat16* Hlo = Hhi + 6 * HTS;                  // [6][HTS]
    float* zs = (float*)(Hhi + 2 * HTS);      // epilogue staging over slots 2-3 (dead)

    const uint32_t* __restrict__ gW0 =
        (const uint32_t*)(g_Wh0[layer] + (size_t)blockIdx.x * 32768);
    const uint32_t* __restrict__ gW1 =
        (const uint32_t*)(g_Wh1[layer] + (size_t)blockIdx.x * 32768);
    float* __restrict__ cbuf = g_cS[layer];
    float* __restrict__ yout = layer ? dout : g_y0;

    int tid = threadIdx.x, warp = tid >> 5, lane = tid & 31;
    int wm = warp & 3, wn = warp >> 2;
    int gg = lane >> 2, tg = lane & 3;
    int n0 = blockIdx.x * 32;
    int ar = wm * 16 + gg;

    // One-time W slice load: 64KB hi + 64KB lo
    for (int i = tid * 4; i < RW_U; i += 1024) {
        cp16(&W0u[i], gW0 + i);
        cp16(&W1u[i], gW1 + i);
    }
    asm volatile("cp.async.commit_group;\n");

    int lb0 = g_len[tid >> 3];
    int lb1 = g_len[32 + (tid >> 3)];

    // staging geometry: each thread copies one 16B chunk per array per tile
    int srow = tid >> 2, scol = (tid & 3) * 8;

    for (int t = 0; t < TT; t++) {
        const __nv_bfloat16* __restrict__ hinH = g_h0[layer][t & 1];
        const __nv_bfloat16* __restrict__ hinL = g_h1[layer][t & 1];
        __nv_bfloat16* __restrict__ houtH = g_h0[layer][(t & 1) ^ 1];
        __nv_bfloat16* __restrict__ houtL = g_h1[layer][(t & 1) ^ 1];

        float acc[32];
#pragma unroll
        for (int i = 0; i < 32; i++) acc[i] = 0.f;

        auto stage_tile = [&](int tile) {
            int slot = tile % 6;
            int kt = tile * 32;
            cp16(Hhi + slot * HTS + srow * 40 + scol, hinH + (size_t)srow * HH + kt + scol);
            cp16(Hlo + slot * HTS + srow * 40 + scol, hinL + (size_t)srow * HH + kt + scol);
        };

        // prologue: pairs 0 and 1 (tiles 0..3), one commit group per pair
        stage_tile(0); stage_tile(1);
        asm volatile("cp.async.commit_group;\n");
        stage_tile(2); stage_tile(3);
        asm volatile("cp.async.commit_group;\n");

        auto compute_tile = [&](int tile) {
            int slot = tile % 6;
            const __nv_bfloat16* ch = Hhi + slot * HTS;
            const __nv_bfloat16* cl = Hlo + slot * HTS;
            float* abase = acc + ((tile & 1) * 2) * 8;
#pragma unroll
            for (int s = 0; s < 2; s++) {
                int k0 = s * 16 + 2 * tg;
                uint32_t a_hi[4], a_lo[4];
                a_hi[0] = *(const uint32_t*)(ch + ar * 40 + k0);
                a_hi[1] = *(const uint32_t*)(ch + (ar + 8) * 40 + k0);
                a_hi[2] = *(const uint32_t*)(ch + ar * 40 + k0 + 8);
                a_hi[3] = *(const uint32_t*)(ch + (ar + 8) * 40 + k0 + 8);
                a_lo[0] = *(const uint32_t*)(cl + ar * 40 + k0);
                a_lo[1] = *(const uint32_t*)(cl + (ar + 8) * 40 + k0);
                a_lo[2] = *(const uint32_t*)(cl + ar * 40 + k0 + 8);
                a_lo[3] = *(const uint32_t*)(cl + (ar + 8) * 40 + k0 + 8);
                float* ac = abase + s * 8;
#pragma unroll
                for (int nt = 0; nt < 2; nt++) {
                    int fi = (((tile * 2 + s) * 2 + nt) * 2 + wn) * 32 + lane;
                    uint2 bh = ((const uint2*)W0u)[fi];
                    uint2 bl = ((const uint2*)W1u)[fi];
                    mma16(ac + nt * 4, a_hi, bh);
                    mma16(ac + nt * 4, a_hi, bl);
                    mma16(ac + nt * 4, a_lo, bh);
                }
            }
        };

        for (int p = 0; p < 16; p++) {
            if (p < 15) asm volatile("cp.async.wait_group 1;\n");
            else        asm volatile("cp.async.wait_group 0;\n");
            __syncthreads();          // pair p ready AND compute(p-1) done everywhere

            if (p < 14) {             // prefetch pair p+2
                stage_tile(2 * p + 4); stage_tile(2 * p + 5);
                asm volatile("cp.async.commit_group;\n");
            }
            compute_tile(2 * p);
            compute_tile(2 * p + 1);
        }

        // Reduce 4 accumulator banks
        float accf[8];
#pragma unroll
        for (int j = 0; j < 8; j++)
            accf[j] = (acc[j] + acc[8 + j]) + (acc[16 + j] + acc[24 + j]);

        // Stage accumulators (zs over slots 2-3: tiles 26/27, dead) for gather
#pragma unroll
        for (int nt = 0; nt < 2; nt++) {
            int col = wn * 16 + nt * 8 + 2 * tg;
            int row = wm * 16 + gg;
            zs[row * 32 + col]           = accf[nt * 4 + 0];
            zs[row * 32 + col + 1]       = accf[nt * 4 + 1];
            zs[(row + 8) * 32 + col]     = accf[nt * 4 + 2];
            zs[(row + 8) * 32 + col + 1] = accf[nt * 4 + 3];
        }
        __syncthreads();

        // Fused gate epilogue: compute + store h first, overlap c/y with barrier
        float csel[2], ysel[2];
#pragma unroll
        for (int rr = 0; rr < 2; rr++) {
            int it = tid + (rr << 8);
            int b = it >> 3, u = it & 7;
            int uglob = (n0 >> 2) + u;
            int hidx = b * HH + uglob;
            float4 zp = *(const float4*)(g_Z + ((size_t)b * TT + t) * NG + n0 + u * 4);
            float zi = zs[b * 32 + u * 4 + 0] + zp.x;
            float zj = zs[b * 32 + u * 4 + 1] + zp.y;
            float zf = zs[b * 32 + u * 4 + 2] + zp.z;
            float zo = zs[b * 32 + u * 4 + 3] + zp.w;

            float co = cbuf[hidx];

            float ig = sigm(zi);
            float fg = sigm(zf + 1.0f);     // FORGET_BIAS
            float og = sigm(zo);
            float cn = co * fg + ig * tanhf(zj);
            float hn = tanhf(cn) * og;

            int lb = rr ? lb1 : lb0;
            bool m = t < lb;

            __nv_bfloat16 hb, lbf;
            if (m) {
                hb = __float2bfloat16_rn(hn);
                lbf = __float2bfloat16_rn(hn - __bfloat162float(hb));
            } else {
                hb = hinH[hidx];
                lbf = hinL[hidx];
            }
            houtH[hidx] = hb;               // cross-CTA data: store before arrive
            houtL[hidx] = lbf;
            csel[rr] = m ? cn : co;
            ysel[rr] = m ? hn : 0.f;
        }

        // Split grid barrier: arrive, overlap private c/y stores, then wait.
        unsigned e = (unsigned)(layer * TT + t);
        __threadfence();
        __syncthreads();
        if (tid == 0) {
            if (atomicInc(&g_count, NBLK - 1) == NBLK - 1) g_gen = e + 1;
        }
#pragma unroll
        for (int rr = 0; rr < 2; rr++) {
            int it = tid + (rr << 8);
            int b = it >> 3, u = it & 7;
            int uglob = (n0 >> 2) + u;
            cbuf[b * HH + uglob] = csel[rr];
            yout[((size_t)b * TT + t) * HH + uglob] = ysel[rr];
        }
        if (tid == 0) {
            while (g_gen <= e) __nanosleep(64);
        }
        __threadfence();
        __syncthreads();
    }
}

// ---------------------------------------------------------------------------
// Copy final h/c stacks into d_out after y1. T=512 even -> final h in buffer 0.
// h reconstructed as hi + lo (error ~2^-17, well inside tolerance).
// ---------------------------------------------------------------------------
__global__ void finalize_kernel(float* __restrict__ dout) {
    int i = blockIdx.x * 256 + threadIdx.x;
    const size_t YN = (size_t)BB * TT * HH;
    if (i < 2 * BB * HH) {
        int layer = i >> 16;       // BB*HH = 65536 per layer
        int j = i & 65535;
        dout[YN + i] = __bfloat162float(g_h0[layer][0][j]) +
                       __bfloat162float(g_h1[layer][0][j]);
        dout[YN + 2 * BB * HH + i] = g_cS[layer][j];
    }
}

// ---------------------------------------------------------------------------
// kernel_launch: identify inputs by element count, 7 graph nodes.
// Node 4 = recurrent_kernel(layer 0) -> ncu capture slot.
// ---------------------------------------------------------------------------
extern "C" void kernel_launch(void* const* d_in, const int* in_sizes, int n_in,
                              void* d_out, int out_size) {
    int ix = -1, il = -1, iw[2] = {-1, -1}, ib[2] = {-1, -1};
    for (int i = 0; i < n_in; i++) {
        int n = in_sizes[i];
        if (n == BB * TT * DD)            { if (ix < 0) ix = i; }
        else if (n == BB)                 { if (il < 0) il = i; }
        else if (n == (DD + HH) * NG)     { if (iw[0] < 0) iw[0] = i; else if (iw[1] < 0) iw[1] = i; }
        else if (n == NG)                 { if (ib[0] < 0) ib[0] = i; else if (ib[1] < 0) ib[1] = i; }
    }
    if (ix < 0) ix = 0;
    if (il < 0) il = 1;
    if (iw[0] < 0) iw[0] = 2;
    if (ib[0] < 0) ib[0] = 3;
    if (iw[1] < 0) iw[1] = 4;
    if (ib[1] < 0) ib[1] = 5;

    const float*     x    = (const float*)d_in[ix];
    const long long* lens = (const long long*)d_in[il];
    const float*     W0   = (const float*)d_in[iw[0]];
    const float*     b0   = (const float*)d_in[ib[0]];
    const float*     W1   = (const float*)d_in[iw[1]];
    const float*     b1   = (const float*)d_in[ib[1]];
    float*           out  = (float*)d_out;

    cudaFuncSetAttribute(recurrent_kernel,
                         cudaFuncAttributeMaxDynamicSharedMemorySize, RSMEM_BYTES);
    cudaFuncSetAttribute(pregemm_kernel,
                         cudaFuncAttributeMaxDynamicSharedMemorySize, PGSMEM_BYTES);

    pack_kernel<<<32768, 256>>>(W0, b0, 0, lens);                 // 1 (incl. setup)
    pack_kernel<<<32768, 256>>>(W1, b1, 1, lens);                 // 2

    pregemm_kernel<<<dim3(32, 512), 256, PGSMEM_BYTES>>>(x, 0);   // 3
    recurrent_kernel<<<NBLK, 256, RSMEM_BYTES>>>(0, out);         // 4 <- ncu capture

    pregemm_kernel<<<dim3(32, 512), 256, PGSMEM_BYTES>>>(x, 1);   // 5
    recurrent_kernel<<<NBLK, 256, RSMEM_BYTES>>>(1, out);         // 6

    finalize_kernel<<<512, 256>>>(out);                           // 7
}

// round 17
// speedup vs baseline: 1.6208x; 1.0664x over previous
#include <cuda_runtime.h>
#include <cuda_bf16.h>
#include <cstdint>

// Problem constants
#define BB 64
#define TT 512
#define DD 1024
#define HH 1024
#define NG 4096   // 4*H
#define KT 1024   // K depth of every GEMM (D == H == 1024)
#define NBLK 128  // CTAs in recurrent kernel (each owns 32 packed gate cols)

// ---------------------------------------------------------------------------
// Device-global scratch (no runtime allocation allowed)
// ---------------------------------------------------------------------------
__device__ float g_Z  [(size_t)BB * TT * NG];   // 512 MB: precomputed x-part of gates (packed cols)
__device__ float g_y0 [(size_t)BB * TT * HH];   // 128 MB: layer-0 outputs (layer-1 inputs)
__device__ __nv_bfloat16 g_Wx0[2][(size_t)KT * NG];  // input weights hi (bf16), fragment-major
__device__ __nv_bfloat16 g_Wx1[2][(size_t)KT * NG];  // input weights lo residual (bf16)
__device__ __nv_bfloat16 g_Wh0[2][(size_t)KT * NG];  // recurrent weights hi (bf16), fragment-major
__device__ __nv_bfloat16 g_Wh1[2][(size_t)KT * NG];  // recurrent weights lo residual (bf16)
__device__ float g_bp [2][NG];                  // packed bias per layer
__device__ __nv_bfloat16 g_h0[2][2][BB * HH];   // h hi  [layer][pingpong]
__device__ __nv_bfloat16 g_h1[2][2][BB * HH];   // h lo
__device__ float g_cS [2][BB * HH];             // c state (written once at kernel end)
__device__ int   g_len[BB];                     // normalized lengths (int32)

// Grid barrier state
__device__ volatile unsigned g_gen;
__device__ unsigned g_count;

// ---------------------------------------------------------------------------
// Helpers
// ---------------------------------------------------------------------------

// m16n8k16 bf16 MMA, fp32 accumulate. C layout identical to m16n8k8.
__device__ __forceinline__ void mma16(float* c, const uint32_t* a, uint2 b) {
    asm volatile(
        "mma.sync.aligned.m16n8k16.row.col.f32.bf16.bf16.f32 "
        "{%0,%1,%2,%3},{%4,%5,%6,%7},{%8,%9},{%0,%1,%2,%3};\n"
        : "+f"(c[0]), "+f"(c[1]), "+f"(c[2]), "+f"(c[3])
        : "r"(a[0]), "r"(a[1]), "r"(a[2]), "r"(a[3]), "r"(b.x), "r"(b.y));
}

__device__ __forceinline__ void cp16(void* smem_dst, const void* gmem_src) {
    unsigned s = (unsigned)__cvta_generic_to_shared(smem_dst);
    asm volatile("cp.async.cg.shared.global [%0], [%1], 16;\n" :: "r"(s), "l"(gmem_src));
}

__device__ __forceinline__ float sigm(float x) { return 1.0f / (1.0f + __expf(-x)); }

// Split packed pair (x = k-even value, y = k-odd value) into bf16 hi + bf16 lo.
__device__ __forceinline__ void split2(float x, float y, uint32_t& hi, uint32_t& lo) {
    __nv_bfloat162 h = __floats2bfloat162_rn(x, y);
    float2 q = __bfloat1622float2(h);
    __nv_bfloat162 l = __floats2bfloat162_rn(x - q.x, y - q.y);
    hi = *reinterpret_cast<uint32_t*>(&h);
    lo = *reinterpret_cast<uint32_t*>(&l);
}

// ---------------------------------------------------------------------------
// Weight packing with bf16 hi/lo split, MMA-fragment-major (m16n8k16).
// (unchanged from R9/R12; validated)
// ---------------------------------------------------------------------------
__global__ void pack_kernel(const float* __restrict__ W, const float* __restrict__ b,
                            int layer, const long long* __restrict__ l64) {
    if (layer == 0) {
        int si = blockIdx.x * 256 + threadIdx.x;
        if (si < 131072) {                      // zero h hi/lo (all buffers) + cS
            ((uint32_t*)g_h0)[si] = 0u;
            ((uint32_t*)g_h1)[si] = 0u;
            ((float*)g_cS)[si] = 0.f;
        }
        if (blockIdx.x == 0 && threadIdx.x < BB) {
            bool bad = false;
            for (int k = 0; k < 32; k++) {
                long long v = l64[k];
                if (v < 1 || v > TT) bad = true;
            }
            int L = bad ? ((const int*)l64)[threadIdx.x] : (int)l64[threadIdx.x];
            g_len[threadIdx.x] = L;
        }
        if (blockIdx.x == 1 && threadIdx.x == 0) { g_gen = 0; g_count = 0; }
    }

    int idx = blockIdx.x * 256 + threadIdx.x;
    if (idx < 2 * KT * NG) {
        int k = idx >> 12;        // row 0..2047
        int p = idx & 4095;       // packed column (u*4+g)
        int u = p >> 2, g = p & 3;
        float v  = W[(size_t)k * NG + g * HH + u];
        __nv_bfloat16 hb = __float2bfloat16_rn(v);
        __nv_bfloat16 lb = __float2bfloat16_rn(v - __bfloat162float(hb));
        if (k < KT) {
            int nb = p >> 7, c = p & 127;
            int wn = (c >> 6) & 1, cc = c & 63, nt = cc >> 3, gg = cc & 7;
            int kt = k >> 5, krel = k & 31;
            int s = krel >> 4, kr = krel & 15;
            int rb = kr >> 3, tg = (kr & 7) >> 1, kb = kr & 1;
            int lane = gg * 4 + tg;
            size_t d = (size_t)nb * 131072 +
                       ((((((size_t)(kt * 2 + s) * 8 + nt) * 2 + wn) * 32 + lane) * 2 + rb) * 2 + kb);
            g_Wx0[layer][d] = hb;
            g_Wx1[layer][d] = lb;
        } else {
            int kk = k - KT;
            int n0b = p >> 5, c = p & 31;
            int wn = c >> 4, nt = (c >> 3) & 1, gg = c & 7;
            int kt = kk >> 5, krel = kk & 31;
            int s = krel >> 4, kr = krel & 15;
            int rb = kr >> 3, tg = (kr & 7) >> 1, kb = kr & 1;
            int lane = gg * 4 + tg;
            size_t d = (size_t)n0b * 32768 +
                       ((((((size_t)(kt * 2 + s) * 2 + nt) * 2 + wn) * 32 + lane) * 2 + rb) * 2 + kb);
            g_Wh0[layer][d] = hb;
            g_Wh1[layer][d] = lb;
        }
    }
    if (idx < NG) {
        int u = idx >> 2, g = idx & 3;
        g_bp[layer][idx] = b[g * HH + u];
    }
}

// ---------------------------------------------------------------------------
// Pre-GEMM, bf16x3 split, cp.async double-buffered, fragment-major W.
// (unchanged from R9/R12)
// ---------------------------------------------------------------------------
#define PG_A  2560            // 64*40 floats
#define PG_WU 2048            // uint32 per ktile per level
#define PGSMEM_BYTES ((2 * PG_A + 4 * PG_WU) * 4)

__global__ __launch_bounds__(256, 2)
void pregemm_kernel(const float* __restrict__ x, int layer) {
    extern __shared__ float psm[];
    float*    a_b  = psm;                                  // [2][PG_A]
    uint32_t* w0_b = (uint32_t*)(psm + 2 * PG_A);          // [2][PG_WU] hi
    uint32_t* w1_b = (uint32_t*)(psm + 2 * PG_A) + 2 * PG_WU; // [2][PG_WU] lo

    const float* __restrict__ A = layer ? g_y0 : x;
    const uint32_t* __restrict__ gW0 =
        (const uint32_t*)(g_Wx0[layer] + (size_t)blockIdx.x * 131072);
    const uint32_t* __restrict__ gW1 =
        (const uint32_t*)(g_Wx1[layer] + (size_t)blockIdx.x * 131072);

    int tid = threadIdx.x, warp = tid >> 5, lane = tid & 31;
    int wm = warp & 3, wn = warp >> 2;
    int gg = lane >> 2, tg = lane & 3;
    size_t m0 = (size_t)blockIdx.y * 64;
    int n0 = blockIdx.x * 128;

    float acc[32];
#pragma unroll
    for (int i = 0; i < 32; i++) acc[i] = 0.f;

    auto load_stage = [&](int ktile, int s) {
        float*    a_s = a_b + s * PG_A;
        uint32_t* w0s = w0_b + s * PG_WU;
        uint32_t* w1s = w1_b + s * PG_WU;
        int kt = ktile * 32;
#pragma unroll
        for (int r = 0; r < 2; r++) {                  // A 64x32 raw fp32, stride 40
            int q = tid + (r << 8);
            int row = q >> 3, c = (q & 7) << 2;
            cp16(a_s + row * 40 + c, A + (m0 + row) * KT + kt + c);
        }
#pragma unroll
        for (int r = 0; r < 2; r++) {                  // W hi + lo, linear fragment-major
            int i = tid * 4 + r * 1024;
            cp16(w0s + i, gW0 + ktile * PG_WU + i);
            cp16(w1s + i, gW1 + ktile * PG_WU + i);
        }
        asm volatile("cp.async.commit_group;\n");
    };

    load_stage(0, 0);
    int buf = 0;
    for (int ktile = 0; ktile < 32; ktile++) {
        if (ktile < 31) {
            load_stage(ktile + 1, buf ^ 1);
            asm volatile("cp.async.wait_group 1;\n");
        } else {
            asm volatile("cp.async.wait_group 0;\n");
        }
        __syncthreads();

        const float*    a_s = a_b + buf * PG_A;
        const uint2*    w0s = (const uint2*)(w0_b + buf * PG_WU);
        const uint2*    w1s = (const uint2*)(w1_b + buf * PG_WU);
        int ar = wm * 16 + gg;
#pragma unroll
        for (int s = 0; s < 2; s++) {
            int k0 = s * 16 + 2 * tg;
            float2 p0 = *(const float2*)(a_s + ar * 40 + k0);
            float2 p1 = *(const float2*)(a_s + (ar + 8) * 40 + k0);
            float2 p2 = *(const float2*)(a_s + ar * 40 + k0 + 8);
            float2 p3 = *(const float2*)(a_s + (ar + 8) * 40 + k0 + 8);
            uint32_t a_hi[4], a_lo[4];
            split2(p0.x, p0.y, a_hi[0], a_lo[0]);
            split2(p1.x, p1.y, a_hi[1], a_lo[1]);
            split2(p2.x, p2.y, a_hi[2], a_lo[2]);
            split2(p3.x, p3.y, a_hi[3], a_lo[3]);
#pragma unroll
            for (int nt = 0; nt < 8; nt++) {
                int fi = ((s * 8 + nt) * 2 + wn) * 32 + lane;
                uint2 bh = w0s[fi];
                uint2 bl = w1s[fi];
                mma16(acc + nt * 4, a_hi, bh);
                mma16(acc + nt * 4, a_hi, bl);
                mma16(acc + nt * 4, a_lo, bh);
            }
        }
        __syncthreads();
        buf ^= 1;
    }

#pragma unroll
    for (int nt = 0; nt < 8; nt++) {
        int col = n0 + wn * 64 + nt * 8 + 2 * tg;
        size_t row = m0 + wm * 16 + gg;
        float bv0 = g_bp[layer][col], bv1 = g_bp[layer][col + 1];
        g_Z[row * NG + col]           = acc[nt * 4 + 0] + bv0;
        g_Z[row * NG + col + 1]       = acc[nt * 4 + 1] + bv1;
        g_Z[(row + 8) * NG + col]     = acc[nt * 4 + 2] + bv0;
        g_Z[(row + 8) * NG + col + 1] = acc[nt * 4 + 3] + bv1;
    }
}

// ---------------------------------------------------------------------------
// Persistent recurrent kernel, bf16x3 split, producer-split h, register-
// resident c/prev-h, smem-prefetched Z, 8 independent accumulator banks.
// Smem: W 128KB + h slots 60KB + zbuf 8KB = 196KB.
// ---------------------------------------------------------------------------
#define RW_U 16384                    // uint32 per level per CTA
#define HTS  2560                     // bf16 per h tile slot (64 rows * stride 40)
#define ZB_F 2048                     // zbuf floats (64 rows * 32 cols)
#define RSMEM_BYTES (2 * RW_U * 4 + 12 * HTS * 2 + ZB_F * 4)

__global__ __launch_bounds__(256, 1)
void recurrent_kernel(int layer, float* __restrict__ dout) {
    extern __shared__ float sm[];
    uint32_t* W0u = (uint32_t*)sm;            // hi fragments (64KB)
    uint32_t* W1u = W0u + RW_U;               // lo fragments (64KB)
    __nv_bfloat16* Hhi = (__nv_bfloat16*)(W1u + RW_U);   // [6][HTS]
    __nv_bfloat16* Hlo = Hhi + 6 * HTS;                  // [6][HTS]
    float* zbuf = (float*)(Hlo + 6 * HTS);    // [64][32] prefetched g_Z slice
    float* zs = (float*)(Hhi + 2 * HTS);      // epilogue staging over slots 2-3 (dead)

    const uint32_t* __restrict__ gW0 =
        (const uint32_t*)(g_Wh0[layer] + (size_t)blockIdx.x * 32768);
    const uint32_t* __restrict__ gW1 =
        (const uint32_t*)(g_Wh1[layer] + (size_t)blockIdx.x * 32768);
    float* __restrict__ yout = layer ? dout : g_y0;

    int tid = threadIdx.x, warp = tid >> 5, lane = tid & 31;
    int wm = warp & 3, wn = warp >> 2;
    int gg = lane >> 2, tg = lane & 3;
    int n0 = blockIdx.x * 32;
    int ar = wm * 16 + gg;

    // One-time W slice load: 64KB hi + 64KB lo
    for (int i = tid * 4; i < RW_U; i += 1024) {
        cp16(&W0u[i], gW0 + i);
        cp16(&W1u[i], gW1 + i);
    }
    asm volatile("cp.async.commit_group;\n");

    int lb0 = g_len[tid >> 3];
    int lb1 = g_len[32 + (tid >> 3)];

    // Register-resident state for this thread's 2 (b, unit) items.
    float creg[2] = {0.f, 0.f};
    __nv_bfloat16 phb[2], plb[2];            // previous h (hi, lo) bf16 — exact bits
    phb[0] = phb[1] = __float2bfloat16_rn(0.f);
    plb[0] = plb[1] = __float2bfloat16_rn(0.f);

    // staging geometry: each thread copies one 16B chunk per array per tile
    int srow = tid >> 2, scol = (tid & 3) * 8;
    // zbuf staging: 512 chunks of 16B / 256 threads = 2 each
    int zrow0 = tid >> 3,           zcol0 = (tid & 7) << 2;
    int zrow1 = (tid + 256) >> 3,   zcol1 = ((tid + 256) & 7) << 2;

    for (int t = 0; t < TT; t++) {
        const __nv_bfloat16* __restrict__ hinH = g_h0[layer][t & 1];
        const __nv_bfloat16* __restrict__ hinL = g_h1[layer][t & 1];
        __nv_bfloat16* __restrict__ houtH = g_h0[layer][(t & 1) ^ 1];
        __nv_bfloat16* __restrict__ houtL = g_h1[layer][(t & 1) ^ 1];

        float acc[64];
#pragma unroll
        for (int i = 0; i < 64; i++) acc[i] = 0.f;

        auto stage_tile = [&](int tile) {
            int slot = tile % 6;
            int kt = tile * 32;
            cp16(Hhi + slot * HTS + srow * 40 + scol, hinH + (size_t)srow * HH + kt + scol);
            cp16(Hlo + slot * HTS + srow * 40 + scol, hinL + (size_t)srow * HH + kt + scol);
        };

        // prologue: pair 0; then pair 1 + zbuf prefetch (g_Z slice for this t)
        stage_tile(0); stage_tile(1);
        asm volatile("cp.async.commit_group;\n");
        stage_tile(2); stage_tile(3);
        cp16(zbuf + zrow0 * 32 + zcol0, g_Z + ((size_t)zrow0 * TT + t) * NG + n0 + zcol0);
        cp16(zbuf + zrow1 * 32 + zcol1, g_Z + ((size_t)zrow1 * TT + t) * NG + n0 + zcol1);
        asm volatile("cp.async.commit_group;\n");

        auto compute_tile = [&](int tile) {
            int slot = tile % 6;
            const __nv_bfloat16* ch = Hhi + slot * HTS;
            const __nv_bfloat16* cl = Hlo + slot * HTS;
#pragma unroll
            for (int s = 0; s < 2; s++) {
                int k0 = s * 16 + 2 * tg;
                uint32_t a_hi[4], a_lo[4];
                a_hi[0] = *(const uint32_t*)(ch + ar * 40 + k0);
                a_hi[1] = *(const uint32_t*)(ch + (ar + 8) * 40 + k0);
                a_hi[2] = *(const uint32_t*)(ch + ar * 40 + k0 + 8);
                a_hi[3] = *(const uint32_t*)(ch + (ar + 8) * 40 + k0 + 8);
                a_lo[0] = *(const uint32_t*)(cl + ar * 40 + k0);
                a_lo[1] = *(const uint32_t*)(cl + (ar + 8) * 40 + k0);
                a_lo[2] = *(const uint32_t*)(cl + ar * 40 + k0 + 8);
                a_lo[3] = *(const uint32_t*)(cl + (ar + 8) * 40 + k0 + 8);
                float* ah = acc + ((tile & 1) * 2 + s) * 16;   // hi bank
                float* ac = ah + 8;                            // correction bank
#pragma unroll
                for (int nt = 0; nt < 2; nt++) {
                    int fi = (((tile * 2 + s) * 2 + nt) * 2 + wn) * 32 + lane;
                    uint2 bh = ((const uint2*)W0u)[fi];
                    uint2 bl = ((const uint2*)W1u)[fi];
                    mma16(ah + nt * 4, a_hi, bh);
                    mma16(ac + nt * 4, a_hi, bl);
                    mma16(ac + nt * 4, a_lo, bh);
                }
            }
        };

        for (int p = 0; p < 16; p++) {
            if (p < 15) asm volatile("cp.async.wait_group 1;\n");
            else        asm volatile("cp.async.wait_group 0;\n");
            __syncthreads();          // pair p ready AND compute(p-1) done everywhere

            if (p < 14) {             // prefetch pair p+2
                stage_tile(2 * p + 4); stage_tile(2 * p + 5);
                asm volatile("cp.async.commit_group;\n");
            }
            compute_tile(2 * p);
            compute_tile(2 * p + 1);
        }

        // Reduce 8 accumulator banks
        float accf[8];
#pragma unroll
        for (int j = 0; j < 8; j++)
            accf[j] = ((acc[j] + acc[8 + j]) + (acc[16 + j] + acc[24 + j])) +
                      ((acc[32 + j] + acc[40 + j]) + (acc[48 + j] + acc[56 + j]));

        // Stage accumulators (zs over slots 2-3: tiles 26/27, dead) for gather
#pragma unroll
        for (int nt = 0; nt < 2; nt++) {
            int col = wn * 16 + nt * 8 + 2 * tg;
            int row = wm * 16 + gg;
            zs[row * 32 + col]           = accf[nt * 4 + 0];
            zs[row * 32 + col + 1]       = accf[nt * 4 + 1];
            zs[(row + 8) * 32 + col]     = accf[nt * 4 + 2];
            zs[(row + 8) * 32 + col + 1] = accf[nt * 4 + 3];
        }
        __syncthreads();

        // Fused gate epilogue: everything from smem/registers; store h, then
        // overlap y store with the grid barrier.
        float ysel[2];
#pragma unroll
        for (int rr = 0; rr < 2; rr++) {
            int it = tid + (rr << 8);
            int b = it >> 3, u = it & 7;
            int uglob = (n0 >> 2) + u;
            int hidx = b * HH + uglob;
            float zi = zs[b * 32 + u * 4 + 0] + zbuf[b * 32 + u * 4 + 0];
            float zj = zs[b * 32 + u * 4 + 1] + zbuf[b * 32 + u * 4 + 1];
            float zf = zs[b * 32 + u * 4 + 2] + zbuf[b * 32 + u * 4 + 2];
            float zo = zs[b * 32 + u * 4 + 3] + zbuf[b * 32 + u * 4 + 3];

            float co = creg[rr];

            float ig = sigm(zi);
            float fg = sigm(zf + 1.0f);     // FORGET_BIAS
            float og = sigm(zo);
            float cn = co * fg + ig * tanhf(zj);
            float hn = tanhf(cn) * og;

            int lb = rr ? lb1 : lb0;
            bool m = t < lb;

            __nv_bfloat16 hb, lbf;
            if (m) {
                hb = __float2bfloat16_rn(hn);
                lbf = __float2bfloat16_rn(hn - __bfloat162float(hb));
            } else {
                hb = phb[rr];
                lbf = plb[rr];
            }
            houtH[hidx] = hb;               // cross-CTA data: store before arrive
            houtL[hidx] = lbf;
            phb[rr] = hb;
            plb[rr] = lbf;
            creg[rr] = m ? cn : co;
            ysel[rr] = m ? hn : 0.f;
        }

        // Split grid barrier: arrive, overlap y stores, then wait.
        unsigned e = (unsigned)(layer * TT + t);
        __threadfence();
        __syncthreads();
        if (tid == 0) {
            if (atomicInc(&g_count, NBLK - 1) == NBLK - 1) g_gen = e + 1;
        }
#pragma unroll
        for (int rr = 0; rr < 2; rr++) {
            int it = tid + (rr << 8);
            int b = it >> 3, u = it & 7;
            int uglob = (n0 >> 2) + u;
            yout[((size_t)b * TT + t) * HH + uglob] = ysel[rr];
        }
        if (tid == 0) {
            while (g_gen <= e) __nanosleep(64);
        }
        __threadfence();
        __syncthreads();
    }

    // Write final c state for finalize_kernel.
#pragma unroll
    for (int rr = 0; rr < 2; rr++) {
        int it = tid + (rr << 8);
        int b = it >> 3, u = it & 7;
        int uglob = (n0 >> 2) + u;
        g_cS[layer][b * HH + uglob] = creg[rr];
    }
}

// ---------------------------------------------------------------------------
// Copy final h/c stacks into d_out after y1. T=512 even -> final h in buffer 0.
// h reconstructed as hi + lo (error ~2^-17, well inside tolerance).
// ---------------------------------------------------------------------------
__global__ void finalize_kernel(float* __restrict__ dout) {
    int i = blockIdx.x * 256 + threadIdx.x;
    const size_t YN = (size_t)BB * TT * HH;
    if (i < 2 * BB * HH) {
        int layer = i >> 16;       // BB*HH = 65536 per layer
        int j = i & 65535;
        dout[YN + i] = __bfloat162float(g_h0[layer][0][j]) +
                       __bfloat162float(g_h1[layer][0][j]);
        dout[YN + 2 * BB * HH + i] = g_cS[layer][j];
    }
}

// ---------------------------------------------------------------------------
// kernel_launch: identify inputs by element count, 7 graph nodes.
// Node 4 = recurrent_kernel(layer 0) -> ncu capture slot.
// ---------------------------------------------------------------------------
extern "C" void kernel_launch(void* const* d_in, const int* in_sizes, int n_in,
                              void* d_out, int out_size) {
    int ix = -1, il = -1, iw[2] = {-1, -1}, ib[2] = {-1, -1};
    for (int i = 0; i < n_in; i++) {
        int n = in_sizes[i];
        if (n == BB * TT * DD)            { if (ix < 0) ix = i; }
        else if (n == BB)                 { if (il < 0) il = i; }
        else if (n == (DD + HH) * NG)     { if (iw[0] < 0) iw[0] = i; else if (iw[1] < 0) iw[1] = i; }
        else if (n == NG)                 { if (ib[0] < 0) ib[0] = i; else if (ib[1] < 0) ib[1] = i; }
    }
    if (ix < 0) ix = 0;
    if (il < 0) il = 1;
    if (iw[0] < 0) iw[0] = 2;
    if (ib[0] < 0) ib[0] = 3;
    if (iw[1] < 0) iw[1] = 4;
    if (ib[1] < 0) ib[1] = 5;

    const float*     x    = (const float*)d_in[ix];
    const long long* lens = (const long long*)d_in[il];
    const float*     W0   = (const float*)d_in[iw[0]];
    const float*     b0   = (const float*)d_in[ib[0]];
    const float*     W1   = (const float*)d_in[iw[1]];
    const float*     b1   = (const float*)d_in[ib[1]];
    float*           out  = (float*)d_out;

    cudaFuncSetAttribute(recurrent_kernel,
                         cudaFuncAttributeMaxDynamicSharedMemorySize, RSMEM_BYTES);
    cudaFuncSetAttribute(pregemm_kernel,
                         cudaFuncAttributeMaxDynamicSharedMemorySize, PGSMEM_BYTES);

    pack_kernel<<<32768, 256>>>(W0, b0, 0, lens);                 // 1 (incl. setup)
    pack_kernel<<<32768, 256>>>(W1, b1, 1, lens);                 // 2

    pregemm_kernel<<<dim3(32, 512), 256, PGSMEM_BYTES>>>(x, 0);   // 3
    recurrent_kernel<<<NBLK, 256, RSMEM_BYTES>>>(0, out);         // 4 <- ncu capture

    pregemm_kernel<<<dim3(32, 512), 256, PGSMEM_BYTES>>>(x, 1);   // 5
    recurrent_kernel<<<NBLK, 256, RSMEM_BYTES>>>(1, out);         // 6

    finalize_kernel<<<512, 256>>>(out);                           // 7
}